// round 1
// baseline (speedup 1.0000x reference)
#include <cuda_runtime.h>

#define MAXN 100000
#define HID 128
#define CLS 40

// ---------------- scratch (static device memory, no allocations) ----------------
__device__ float g_deg_src[MAXN];                 // becomes c_src after norm_kernel
__device__ float g_deg_dst[MAXN];                 // becomes c_dst after norm_kernel
__device__ float g_tmp [(size_t)MAXN * HID];
__device__ float g_hbuf[(size_t)MAXN * HID];
__device__ float g_agg1[(size_t)MAXN * HID];
__device__ float g_agg2[(size_t)MAXN * HID];

// ---------------- utility ----------------
__global__ void zero_kernel(float* __restrict__ p, size_t count) {
    size_t i = (size_t)blockIdx.x * blockDim.x + threadIdx.x;
    size_t stride = (size_t)gridDim.x * blockDim.x;
    for (; i < count; i += stride) p[i] = 0.f;
}

__global__ void degree_kernel(const int* __restrict__ src, const int* __restrict__ dst, int e) {
    int i = blockIdx.x * blockDim.x + threadIdx.x;
    if (i < e) {
        atomicAdd(&g_deg_src[src[i]], 1.f);
        atomicAdd(&g_deg_dst[dst[i]], 1.f);
    }
}

__global__ void norm_kernel(int n) {
    int i = blockIdx.x * blockDim.x + threadIdx.x;
    if (i < n) {
        g_deg_src[i] = rsqrtf(fmaxf(g_deg_src[i], 1.f));
        g_deg_dst[i] = rsqrtf(fmaxf(g_deg_dst[i], 1.f));
    }
}

// ---------------- tiled fp32 GEMM:  C[M][128] = (A[M][K] @ B[K][128]) * rowscale[m] ----------------
// BM=64, BN=128, BK=32. 256 threads, each computes 8x4 outputs.
__global__ void gemm_rowscale_kernel(const float* __restrict__ A, const float* __restrict__ B,
                                     const float* __restrict__ rowscale, float* __restrict__ C,
                                     int M, int K) {
    __shared__ __align__(16) float As[64][36];   // padded: row stride 144B (16B aligned, low conflict)
    __shared__ __align__(16) float Bs[32][128];

    const int tid = threadIdx.x;
    const int ty  = tid >> 5;     // 0..7  -> row group of 8
    const int tx  = tid & 31;     // 0..31 -> col group of 4
    const int m0  = blockIdx.x * 64;

    float acc[8][4];
#pragma unroll
    for (int i = 0; i < 8; i++)
#pragma unroll
        for (int j = 0; j < 4; j++) acc[i][j] = 0.f;

    for (int k0 = 0; k0 < K; k0 += 32) {
        // load A tile 64x32 as float4 (coalesced along K)
#pragma unroll
        for (int l = 0; l < 2; l++) {
            int idx = tid + l * 256;            // 0..511
            int m = idx >> 3;                   // 8 float4 per row
            int k = (idx & 7) << 2;
            float4 v = make_float4(0.f, 0.f, 0.f, 0.f);
            int gm = m0 + m;
            if (gm < M) v = *reinterpret_cast<const float4*>(A + (size_t)gm * K + k0 + k);
            *reinterpret_cast<float4*>(&As[m][k]) = v;
        }
        // load B tile 32x128 as float4 (coalesced along N)
#pragma unroll
        for (int l = 0; l < 4; l++) {
            int idx = tid + l * 256;            // 0..1023
            int k = idx >> 5;                   // 32 float4 per row
            int nn = (idx & 31) << 2;
            *reinterpret_cast<float4*>(&Bs[k][nn]) =
                *reinterpret_cast<const float4*>(B + (size_t)(k0 + k) * 128 + nn);
        }
        __syncthreads();
#pragma unroll
        for (int kk = 0; kk < 32; kk++) {
            float4 bv = *reinterpret_cast<const float4*>(&Bs[kk][tx << 2]);  // LDS.128, conflict-free
#pragma unroll
            for (int i = 0; i < 8; i++) {
                float a = As[(ty << 3) + i][kk];   // uniform within warp -> broadcast
                acc[i][0] = fmaf(a, bv.x, acc[i][0]);
                acc[i][1] = fmaf(a, bv.y, acc[i][1]);
                acc[i][2] = fmaf(a, bv.z, acc[i][2]);
                acc[i][3] = fmaf(a, bv.w, acc[i][3]);
            }
        }
        __syncthreads();
    }
#pragma unroll
    for (int i = 0; i < 8; i++) {
        int gm = m0 + (ty << 3) + i;
        if (gm < M) {
            float s = rowscale[gm];
            float4 o = make_float4(acc[i][0] * s, acc[i][1] * s, acc[i][2] * s, acc[i][3] * s);
            *reinterpret_cast<float4*>(C + (size_t)gm * 128 + (tx << 2)) = o;
        }
    }
}

// ---------------- SpMM scatter: agg[dst] += T[src], one warp per edge ----------------
__global__ void spmm_kernel(const float* __restrict__ T, const int* __restrict__ src,
                            const int* __restrict__ dst, float* __restrict__ agg, int e) {
    int gw   = (blockIdx.x * blockDim.x + threadIdx.x) >> 5;
    int lane = threadIdx.x & 31;
    if (gw < e) {
        int s = __ldg(src + gw);
        int d = __ldg(dst + gw);
        float4 v = *reinterpret_cast<const float4*>(T + (size_t)s * 128 + (lane << 2));
        float* base = agg + (size_t)d * 128 + (lane << 2);
        atomicAdd(base + 0, v.x);
        atomicAdd(base + 1, v.y);
        atomicAdd(base + 2, v.z);
        atomicAdd(base + 3, v.w);
    }
}

// ---------------- h = relu(agg * c_dst + b) ----------------
__global__ void post_kernel(const float* __restrict__ agg, const float* __restrict__ b,
                            float* __restrict__ out, int n) {
    size_t total = (size_t)n * HID;
    size_t i = (size_t)blockIdx.x * blockDim.x + threadIdx.x;
    if (i < total) {
        int node = (int)(i >> 7);
        int c = (int)(i & 127);
        float v = agg[i] * g_deg_dst[node] + b[c];
        out[i] = fmaxf(v, 0.f);
    }
}

// ---------------- final: h = agg*c_dst + b1 -> out_h ; logits = relu(h) @ Wc + bc ----------------
// One block per 32 nodes. Wc cached in smem.
__global__ void final_kernel(const float* __restrict__ agg, const float* __restrict__ b1,
                             const float* __restrict__ Wc, const float* __restrict__ bc,
                             float* __restrict__ out_h, float* __restrict__ out_logits, int n) {
    __shared__ float hs[32][HID + 1];     // +1 pad -> conflict-free hs[r][k] reads
    __shared__ float Wcs[HID][CLS];
    __shared__ float bcs[CLS];

    const int tid = threadIdx.x;
    const int n0  = blockIdx.x * 32;

    for (int i = tid; i < HID * CLS; i += 256) Wcs[i / CLS][i % CLS] = Wc[i];
    if (tid < CLS) bcs[tid] = bc[tid];

    for (int i = tid; i < 32 * HID; i += 256) {
        int r = i >> 7, c = i & 127;
        int g = n0 + r;
        if (g < n) {
            float v = agg[(size_t)g * HID + c] * g_deg_dst[g] + b1[c];
            out_h[(size_t)g * HID + c] = v;
            hs[r][c] = fmaxf(v, 0.f);
        } else {
            hs[r][c] = 0.f;
        }
    }
    __syncthreads();

    int r  = tid & 31;      // node within tile
    int cg = tid >> 5;      // 0..7 -> 5 classes each
    int g  = n0 + r;
    if (g < n) {
        float acc[5];
#pragma unroll
        for (int j = 0; j < 5; j++) acc[j] = bcs[cg * 5 + j];
        for (int k = 0; k < HID; k++) {
            float a = hs[r][k];
#pragma unroll
            for (int j = 0; j < 5; j++) acc[j] = fmaf(a, Wcs[k][cg * 5 + j], acc[j]);
        }
#pragma unroll
        for (int j = 0; j < 5; j++) out_logits[(size_t)g * CLS + cg * 5 + j] = acc[j];
    }
}

// ---------------- launch ----------------
extern "C" void kernel_launch(void* const* d_in, const int* in_sizes, int n_in,
                              void* d_out, int out_size) {
    const float* x  = (const float*)d_in[0];
    const int*   src = (const int*)d_in[1];
    const int*   dst = (const int*)d_in[2];
    const float* W0 = (const float*)d_in[3];
    const float* b0 = (const float*)d_in[4];
    const float* W1 = (const float*)d_in[5];
    const float* b1 = (const float*)d_in[6];
    const float* Wc = (const float*)d_in[7];
    const float* bc = (const float*)d_in[8];

    const int n = in_sizes[0] / 256;   // IN_FEATS = 256
    const int e = in_sizes[1];

    float *tmp, *hbuf, *agg1, *agg2, *dsrc, *ddst;
    cudaGetSymbolAddress((void**)&tmp,  g_tmp);
    cudaGetSymbolAddress((void**)&hbuf, g_hbuf);
    cudaGetSymbolAddress((void**)&agg1, g_agg1);
    cudaGetSymbolAddress((void**)&agg2, g_agg2);
    cudaGetSymbolAddress((void**)&dsrc, g_deg_src);
    cudaGetSymbolAddress((void**)&ddst, g_deg_dst);

    float* out_h      = (float*)d_out;
    float* out_logits = out_h + (size_t)n * HID;

    const size_t nh = (size_t)n * HID;

    zero_kernel<<<2048, 256>>>(agg1, nh);
    zero_kernel<<<2048, 256>>>(agg2, nh);
    zero_kernel<<<(n + 255) / 256, 256>>>(dsrc, (size_t)n);
    zero_kernel<<<(n + 255) / 256, 256>>>(ddst, (size_t)n);

    degree_kernel<<<(e + 255) / 256, 256>>>(src, dst, e);
    norm_kernel<<<(n + 255) / 256, 256>>>(n);

    const int gblocks = (n + 63) / 64;

    // layer 0: tmp = (x @ W0) * c_src ; agg1 = scatter ; hbuf = relu(agg1*c_dst + b0)
    gemm_rowscale_kernel<<<gblocks, 256>>>(x, W0, dsrc, tmp, n, 256);
    spmm_kernel<<<(e + 7) / 8, 256>>>(tmp, src, dst, agg1, e);
    post_kernel<<<(int)((nh + 255) / 256), 256>>>(agg1, b0, hbuf, n);

    // layer 1: tmp = (hbuf @ W1) * c_src ; agg2 = scatter
    gemm_rowscale_kernel<<<gblocks, 256>>>(hbuf, W1, dsrc, tmp, n, 128);
    spmm_kernel<<<(e + 7) / 8, 256>>>(tmp, src, dst, agg2, e);

    // final: h -> d_out[0 : n*128], logits -> d_out[n*128 : n*168]
    final_kernel<<<(n + 31) / 32, 256>>>(agg2, b1, Wc, bc, out_h, out_logits, n);
}

// round 2
// speedup vs baseline: 2.5486x; 2.5486x over previous
#include <cuda_runtime.h>
#include <cstdint>

#define MAXN 100000
#define MAXE 1600000
#define HID 128
#define CLS 40

// ---------------- scratch (static device memory, no allocations) ----------------
__device__ int   g_ideg_src[MAXN];
__device__ int   g_ideg_dst[MAXN];
__device__ float g_csrc[MAXN];
__device__ float g_cdst[MAXN];
__device__ int   g_roff[MAXN + 1];
__device__ int   g_cursor[MAXN];
__device__ int   g_bsums[128];
__device__ int   g_csr[MAXE];
__device__ float g_tmp [(size_t)MAXN * HID];
__device__ float g_hbuf[(size_t)MAXN * HID];

// ---------------- utilities ----------------
__global__ void zero_int2_kernel(int* __restrict__ a, int* __restrict__ b, int n) {
    int i = blockIdx.x * blockDim.x + threadIdx.x;
    if (i < n) { a[i] = 0; b[i] = 0; }
}

__global__ void degree_kernel(const int* __restrict__ src, const int* __restrict__ dst, int e) {
    int i = blockIdx.x * blockDim.x + threadIdx.x;
    if (i < e) {
        atomicAdd(&g_ideg_src[src[i]], 1);
        atomicAdd(&g_ideg_dst[dst[i]], 1);
    }
}

__global__ void norm_kernel(int n) {
    int i = blockIdx.x * blockDim.x + threadIdx.x;
    if (i < n) {
        g_csrc[i] = rsqrtf(fmaxf((float)g_ideg_src[i], 1.f));
        g_cdst[i] = rsqrtf(fmaxf((float)g_ideg_dst[i], 1.f));
    }
}

// ---------------- 3-phase exclusive scan of in-degrees -> CSR row offsets ----------------
__global__ void scan1_kernel(const int* __restrict__ deg, int* __restrict__ out,
                             int* __restrict__ bsums, int n) {
    __shared__ int sm[1024];
    int i = blockIdx.x * 1024 + threadIdx.x;
    int v = (i < n) ? deg[i] : 0;
    sm[threadIdx.x] = v;
    __syncthreads();
    for (int off = 1; off < 1024; off <<= 1) {
        int t = (threadIdx.x >= off) ? sm[threadIdx.x - off] : 0;
        __syncthreads();
        sm[threadIdx.x] += t;
        __syncthreads();
    }
    if (i < n) out[i] = sm[threadIdx.x] - v;            // exclusive
    if (threadIdx.x == 1023) bsums[blockIdx.x] = sm[1023];
}

__global__ void scan2_kernel(int* __restrict__ bsums, int nb) {
    __shared__ int sm[128];
    int t = threadIdx.x;
    int v = (t < nb) ? bsums[t] : 0;
    sm[t] = v;
    __syncthreads();
    for (int off = 1; off < 128; off <<= 1) {
        int u = (t >= off) ? sm[t - off] : 0;
        __syncthreads();
        sm[t] += u;
        __syncthreads();
    }
    if (t < nb) bsums[t] = sm[t] - v;                   // exclusive
}

__global__ void scan3_kernel(int* __restrict__ roff, int* __restrict__ cursor,
                             const int* __restrict__ bsums, int n, int e) {
    int i = blockIdx.x * blockDim.x + threadIdx.x;
    if (i < n) {
        int v = roff[i] + bsums[i >> 10];
        roff[i] = v;
        cursor[i] = v;
    }
    if (i == 0) roff[n] = e;
}

__global__ void csr_fill_kernel(const int* __restrict__ src, const int* __restrict__ dst,
                                int* __restrict__ cursor, int* __restrict__ csr, int e) {
    int i = blockIdx.x * blockDim.x + threadIdx.x;
    if (i < e) {
        int d = dst[i];
        int pos = atomicAdd(&cursor[d], 1);
        csr[pos] = src[i];
    }
}

// ---------------- TF32 tensor-core GEMM (3xTF32 split): C = (A[M,K] @ B[K,128]) * rowscale[m]
// BM=128, BN=128, BK=16, 256 threads (8 warps), warp tile 32x64, m16n8k8 mma.
__device__ __forceinline__ void split_tf32(float x, float& hi, float& lo) {
    uint32_t h;
    asm("cvt.rna.tf32.f32 %0, %1;" : "=r"(h) : "f"(x));
    hi = __uint_as_float(h);
    float l = x - hi;
    uint32_t lu;
    asm("cvt.rna.tf32.f32 %0, %1;" : "=r"(lu) : "f"(l));
    lo = __uint_as_float(lu);
}

#define MMA_TF32(d, a, b0v, b1v)                                                 \
    asm volatile("mma.sync.aligned.m16n8k8.row.col.f32.tf32.tf32.f32 "           \
                 "{%0,%1,%2,%3}, {%4,%5,%6,%7}, {%8,%9}, {%0,%1,%2,%3};"         \
                 : "+f"((d)[0]), "+f"((d)[1]), "+f"((d)[2]), "+f"((d)[3])        \
                 : "r"((a)[0]), "r"((a)[1]), "r"((a)[2]), "r"((a)[3]),           \
                   "r"(b0v), "r"(b1v));

#define AS_STRIDE 20
#define BS_STRIDE 136

__global__ __launch_bounds__(256, 2)
void gemm_tf32_kernel(const float* __restrict__ A, const float* __restrict__ B,
                      const float* __restrict__ rowscale, float* __restrict__ C,
                      int M, int K) {
    __shared__ float As_hi[128 * AS_STRIDE];
    __shared__ float As_lo[128 * AS_STRIDE];
    __shared__ float Bs_hi[16 * BS_STRIDE];
    __shared__ float Bs_lo[16 * BS_STRIDE];

    const int tid  = threadIdx.x;
    const int warp = tid >> 5, lane = tid & 31;
    const int wm   = warp >> 1, wn = warp & 1;     // 4x2 warp grid
    const int gid  = lane >> 2, tig = lane & 3;
    const int m0   = blockIdx.x * 128;

    float acc[2][8][4];
#pragma unroll
    for (int mt = 0; mt < 2; mt++)
#pragma unroll
        for (int nt = 0; nt < 8; nt++)
#pragma unroll
            for (int j = 0; j < 4; j++) acc[mt][nt][j] = 0.f;

    for (int k0 = 0; k0 < K; k0 += 16) {
        // A tile 128x16 (4 float4 per row)
#pragma unroll
        for (int l = 0; l < 2; l++) {
            int idx = tid + l * 256;            // 0..511
            int r = idx >> 2;
            int c = (idx & 3) << 2;
            float4 v = make_float4(0.f, 0.f, 0.f, 0.f);
            if (m0 + r < M) v = *reinterpret_cast<const float4*>(A + (size_t)(m0 + r) * K + k0 + c);
            float* ph = As_hi + r * AS_STRIDE + c;
            float* pl = As_lo + r * AS_STRIDE + c;
            split_tf32(v.x, ph[0], pl[0]);
            split_tf32(v.y, ph[1], pl[1]);
            split_tf32(v.z, ph[2], pl[2]);
            split_tf32(v.w, ph[3], pl[3]);
        }
        // B tile 16x128 (32 float4 per row)
#pragma unroll
        for (int l = 0; l < 2; l++) {
            int idx = tid + l * 256;            // 0..511
            int k = idx >> 5;
            int nn = (idx & 31) << 2;
            float4 v = *reinterpret_cast<const float4*>(B + (size_t)(k0 + k) * 128 + nn);
            float* ph = Bs_hi + k * BS_STRIDE + nn;
            float* pl = Bs_lo + k * BS_STRIDE + nn;
            split_tf32(v.x, ph[0], pl[0]);
            split_tf32(v.y, ph[1], pl[1]);
            split_tf32(v.z, ph[2], pl[2]);
            split_tf32(v.w, ph[3], pl[3]);
        }
        __syncthreads();

#pragma unroll
        for (int kk = 0; kk < 16; kk += 8) {
            uint32_t ah[2][4], al[2][4];
#pragma unroll
            for (int mt = 0; mt < 2; mt++) {
                int rb = wm * 32 + mt * 16 + gid;
                int c0 = kk + tig;
                ah[mt][0] = __float_as_uint(As_hi[rb * AS_STRIDE + c0]);
                ah[mt][1] = __float_as_uint(As_hi[(rb + 8) * AS_STRIDE + c0]);
                ah[mt][2] = __float_as_uint(As_hi[rb * AS_STRIDE + c0 + 4]);
                ah[mt][3] = __float_as_uint(As_hi[(rb + 8) * AS_STRIDE + c0 + 4]);
                al[mt][0] = __float_as_uint(As_lo[rb * AS_STRIDE + c0]);
                al[mt][1] = __float_as_uint(As_lo[(rb + 8) * AS_STRIDE + c0]);
                al[mt][2] = __float_as_uint(As_lo[rb * AS_STRIDE + c0 + 4]);
                al[mt][3] = __float_as_uint(As_lo[(rb + 8) * AS_STRIDE + c0 + 4]);
            }
#pragma unroll
            for (int nt = 0; nt < 8; nt++) {
                int cb = wn * 64 + nt * 8 + gid;
                uint32_t bh0 = __float_as_uint(Bs_hi[(kk + tig) * BS_STRIDE + cb]);
                uint32_t bh1 = __float_as_uint(Bs_hi[(kk + tig + 4) * BS_STRIDE + cb]);
                uint32_t bl0 = __float_as_uint(Bs_lo[(kk + tig) * BS_STRIDE + cb]);
                uint32_t bl1 = __float_as_uint(Bs_lo[(kk + tig + 4) * BS_STRIDE + cb]);
#pragma unroll
                for (int mt = 0; mt < 2; mt++) {
                    MMA_TF32(acc[mt][nt], ah[mt], bh0, bh1);
                    MMA_TF32(acc[mt][nt], al[mt], bh0, bh1);
                    MMA_TF32(acc[mt][nt], ah[mt], bl0, bl1);
                }
            }
        }
        __syncthreads();
    }

    // epilogue: scale rows, store float2 pairs
#pragma unroll
    for (int mt = 0; mt < 2; mt++) {
        int r0 = m0 + wm * 32 + mt * 16 + gid;
        int r1 = r0 + 8;
        float s0 = (r0 < M) ? rowscale[r0] : 0.f;
        float s1 = (r1 < M) ? rowscale[r1] : 0.f;
#pragma unroll
        for (int nt = 0; nt < 8; nt++) {
            int c = wn * 64 + nt * 8 + 2 * tig;
            if (r0 < M) {
                float2 o = make_float2(acc[mt][nt][0] * s0, acc[mt][nt][1] * s0);
                *reinterpret_cast<float2*>(C + (size_t)r0 * 128 + c) = o;
            }
            if (r1 < M) {
                float2 o = make_float2(acc[mt][nt][2] * s1, acc[mt][nt][3] * s1);
                *reinterpret_cast<float2*>(C + (size_t)r1 * 128 + c) = o;
            }
        }
    }
}

// ---------------- CSR SpMM: out[v] = (sum_{s in N(v)} T[s]) * c_dst[v] + b  (optional relu)
// One warp per dst node; 4-way unrolled edge loop for MLP.
__global__ void spmm_csr_kernel(const float* __restrict__ T, const int* __restrict__ csr,
                                const int* __restrict__ roff, const float* __restrict__ cdst,
                                const float* __restrict__ bias, float* __restrict__ out,
                                int n, int do_relu) {
    int w    = (blockIdx.x * blockDim.x + threadIdx.x) >> 5;
    int lane = threadIdx.x & 31;
    if (w >= n) return;
    int beg = __ldg(roff + w), end = __ldg(roff + w + 1);

    float4 acc = make_float4(0.f, 0.f, 0.f, 0.f);
    int i = beg;
    for (; i + 4 <= end; i += 4) {
        int s0 = __ldg(csr + i);
        int s1 = __ldg(csr + i + 1);
        int s2 = __ldg(csr + i + 2);
        int s3 = __ldg(csr + i + 3);
        float4 v0 = *reinterpret_cast<const float4*>(T + (size_t)s0 * 128 + (lane << 2));
        float4 v1 = *reinterpret_cast<const float4*>(T + (size_t)s1 * 128 + (lane << 2));
        float4 v2 = *reinterpret_cast<const float4*>(T + (size_t)s2 * 128 + (lane << 2));
        float4 v3 = *reinterpret_cast<const float4*>(T + (size_t)s3 * 128 + (lane << 2));
        acc.x += (v0.x + v1.x) + (v2.x + v3.x);
        acc.y += (v0.y + v1.y) + (v2.y + v3.y);
        acc.z += (v0.z + v1.z) + (v2.z + v3.z);
        acc.w += (v0.w + v1.w) + (v2.w + v3.w);
    }
    for (; i < end; i++) {
        int s = __ldg(csr + i);
        float4 v = *reinterpret_cast<const float4*>(T + (size_t)s * 128 + (lane << 2));
        acc.x += v.x; acc.y += v.y; acc.z += v.z; acc.w += v.w;
    }
    float c = __ldg(cdst + w);
    float4 b = *reinterpret_cast<const float4*>(bias + (lane << 2));
    acc.x = acc.x * c + b.x;
    acc.y = acc.y * c + b.y;
    acc.z = acc.z * c + b.z;
    acc.w = acc.w * c + b.w;
    if (do_relu) {
        acc.x = fmaxf(acc.x, 0.f); acc.y = fmaxf(acc.y, 0.f);
        acc.z = fmaxf(acc.z, 0.f); acc.w = fmaxf(acc.w, 0.f);
    }
    *reinterpret_cast<float4*>(out + (size_t)w * 128 + (lane << 2)) = acc;
}

// ---------------- final: logits = relu(h) @ Wc + bc  (h already in d_out) ----------------
__global__ void final_kernel(const float* __restrict__ h, const float* __restrict__ Wc,
                             const float* __restrict__ bc, float* __restrict__ out_logits, int n) {
    __shared__ float hs[32][HID + 1];
    __shared__ float Wcs[HID][CLS];
    __shared__ float bcs[CLS];

    const int tid = threadIdx.x;
    const int n0  = blockIdx.x * 32;

    for (int i = tid; i < HID * CLS; i += 256) Wcs[i / CLS][i % CLS] = Wc[i];
    if (tid < CLS) bcs[tid] = bc[tid];

    for (int i = tid; i < 32 * HID; i += 256) {
        int r = i >> 7, c = i & 127;
        int g = n0 + r;
        hs[r][c] = (g < n) ? fmaxf(h[(size_t)g * HID + c], 0.f) : 0.f;
    }
    __syncthreads();

    int r  = tid & 31;
    int cg = tid >> 5;
    int g  = n0 + r;
    if (g < n) {
        float acc[5];
#pragma unroll
        for (int j = 0; j < 5; j++) acc[j] = bcs[cg * 5 + j];
        for (int k = 0; k < HID; k++) {
            float a = hs[r][k];
#pragma unroll
            for (int j = 0; j < 5; j++) acc[j] = fmaf(a, Wcs[k][cg * 5 + j], acc[j]);
        }
#pragma unroll
        for (int j = 0; j < 5; j++) out_logits[(size_t)g * CLS + cg * 5 + j] = acc[j];
    }
}

// ---------------- launch ----------------
extern "C" void kernel_launch(void* const* d_in, const int* in_sizes, int n_in,
                              void* d_out, int out_size) {
    const float* x   = (const float*)d_in[0];
    const int*   src = (const int*)d_in[1];
    const int*   dst = (const int*)d_in[2];
    const float* W0  = (const float*)d_in[3];
    const float* b0  = (const float*)d_in[4];
    const float* W1  = (const float*)d_in[5];
    const float* b1  = (const float*)d_in[6];
    const float* Wc  = (const float*)d_in[7];
    const float* bc  = (const float*)d_in[8];

    const int n = in_sizes[0] / 256;   // IN_FEATS = 256
    const int e = in_sizes[1];

    int *ideg_s, *ideg_d, *roff, *cursor, *bsums, *csr;
    float *csrc, *cdst, *tmp, *hbuf;
    cudaGetSymbolAddress((void**)&ideg_s, g_ideg_src);
    cudaGetSymbolAddress((void**)&ideg_d, g_ideg_dst);
    cudaGetSymbolAddress((void**)&roff,   g_roff);
    cudaGetSymbolAddress((void**)&cursor, g_cursor);
    cudaGetSymbolAddress((void**)&bsums,  g_bsums);
    cudaGetSymbolAddress((void**)&csr,    g_csr);
    cudaGetSymbolAddress((void**)&csrc,   g_csrc);
    cudaGetSymbolAddress((void**)&cdst,   g_cdst);
    cudaGetSymbolAddress((void**)&tmp,    g_tmp);
    cudaGetSymbolAddress((void**)&hbuf,   g_hbuf);

    float* out_h      = (float*)d_out;
    float* out_logits = out_h + (size_t)n * HID;

    const int nb = (n + 1023) / 1024;

    // degrees + norms
    zero_int2_kernel<<<(n + 255) / 256, 256>>>(ideg_s, ideg_d, n);
    degree_kernel<<<(e + 255) / 256, 256>>>(src, dst, e);
    norm_kernel<<<(n + 255) / 256, 256>>>(n);

    // CSR (by dst) build
    scan1_kernel<<<nb, 1024>>>(ideg_d, roff, bsums, n);
    scan2_kernel<<<1, 128>>>(bsums, nb);
    scan3_kernel<<<(n + 255) / 256, 256>>>(roff, cursor, bsums, n, e);
    csr_fill_kernel<<<(e + 255) / 256, 256>>>(src, dst, cursor, csr, e);

    const int gblocks = (n + 127) / 128;
    const int sblocks = (int)(((size_t)n * 32 + 255) / 256);

    // layer 0
    gemm_tf32_kernel<<<gblocks, 256>>>(x, W0, csrc, tmp, n, 256);
    spmm_csr_kernel<<<sblocks, 256>>>(tmp, csr, roff, cdst, b0, hbuf, n, 1);

    // layer 1 (h written straight into d_out)
    gemm_tf32_kernel<<<gblocks, 256>>>(hbuf, W1, csrc, tmp, n, 128);
    spmm_csr_kernel<<<sblocks, 256>>>(tmp, csr, roff, cdst, b1, out_h, n, 0);

    // classifier head
    final_kernel<<<(n + 31) / 32, 256>>>(out_h, Wc, bc, out_logits, n);
}

// round 3
// speedup vs baseline: 3.2154x; 1.2616x over previous
#include <cuda_runtime.h>
#include <cuda_bf16.h>
#include <cstdint>

#define MAXN 100000
#define MAXE 1600000
#define HID 128
#define CLS 40

// ---------------- scratch (static device memory, no allocations) ----------------
__device__ int   g_ideg_src[MAXN];
__device__ int   g_ideg_dst[MAXN];
__device__ float g_csrc[MAXN];
__device__ float g_cdst[MAXN];
__device__ int   g_roff[MAXN + 1];
__device__ int   g_cursor[MAXN];
__device__ int   g_bsums[128];
__device__ int   g_csr[MAXE];
__device__ float g_tmp [(size_t)MAXN * HID];
__device__ float g_hbuf[(size_t)MAXN * HID];

// ---------------- utilities ----------------
__global__ void zero_int2_kernel(int* __restrict__ a, int* __restrict__ b, int n) {
    int i = blockIdx.x * blockDim.x + threadIdx.x;
    if (i < n) { a[i] = 0; b[i] = 0; }
}

__global__ void degree_kernel(const int* __restrict__ src, const int* __restrict__ dst, int e) {
    int i = blockIdx.x * blockDim.x + threadIdx.x;
    if (i < e) {
        atomicAdd(&g_ideg_src[src[i]], 1);
        atomicAdd(&g_ideg_dst[dst[i]], 1);
    }
}

// ---------------- 3-phase exclusive scan of in-degrees -> CSR row offsets ----------------
__global__ void scan1_kernel(const int* __restrict__ deg, int* __restrict__ out,
                             int* __restrict__ bsums, int n) {
    __shared__ int sm[1024];
    int i = blockIdx.x * 1024 + threadIdx.x;
    int v = (i < n) ? deg[i] : 0;
    sm[threadIdx.x] = v;
    __syncthreads();
    for (int off = 1; off < 1024; off <<= 1) {
        int t = (threadIdx.x >= off) ? sm[threadIdx.x - off] : 0;
        __syncthreads();
        sm[threadIdx.x] += t;
        __syncthreads();
    }
    if (i < n) out[i] = sm[threadIdx.x] - v;            // exclusive
    if (threadIdx.x == 1023) bsums[blockIdx.x] = sm[1023];
}

__global__ void scan2_kernel(int* __restrict__ bsums, int nb) {
    __shared__ int sm[128];
    int t = threadIdx.x;
    int v = (t < nb) ? bsums[t] : 0;
    sm[t] = v;
    __syncthreads();
    for (int off = 1; off < 128; off <<= 1) {
        int u = (t >= off) ? sm[t - off] : 0;
        __syncthreads();
        sm[t] += u;
        __syncthreads();
    }
    if (t < nb) bsums[t] = sm[t] - v;                   // exclusive
}

// scan3 + degree norms fused
__global__ void scan3_kernel(int* __restrict__ roff, int* __restrict__ cursor,
                             const int* __restrict__ bsums, int n, int e) {
    int i = blockIdx.x * blockDim.x + threadIdx.x;
    if (i < n) {
        int v = roff[i] + bsums[i >> 10];
        roff[i] = v;
        cursor[i] = v;
        g_csrc[i] = rsqrtf(fmaxf((float)g_ideg_src[i], 1.f));
        g_cdst[i] = rsqrtf(fmaxf((float)g_ideg_dst[i], 1.f));
    }
    if (i == 0) roff[n] = e;
}

__global__ void csr_fill_kernel(const int* __restrict__ src, const int* __restrict__ dst,
                                int* __restrict__ cursor, int* __restrict__ csr, int e) {
    int i = blockIdx.x * blockDim.x + threadIdx.x;
    if (i < e) {
        int d = dst[i];
        int pos = atomicAdd(&cursor[d], 1);
        csr[pos] = src[i];
    }
}

// ---------------- bf16 split helpers ----------------
__device__ __forceinline__ void split2_pack(float x, float y, uint32_t& hi, uint32_t& lo) {
    __nv_bfloat16 hx = __float2bfloat16(x);
    __nv_bfloat16 hy = __float2bfloat16(y);
    float rx = x - __bfloat162float(hx);
    float ry = y - __bfloat162float(hy);
    __nv_bfloat162 h2 = __halves2bfloat162(hx, hy);
    __nv_bfloat162 l2 = __floats2bfloat162_rn(rx, ry);
    hi = *reinterpret_cast<uint32_t*>(&h2);
    lo = *reinterpret_cast<uint32_t*>(&l2);
}

#define MMA_BF16(d, a, b0v, b1v)                                                  \
    asm volatile("mma.sync.aligned.m16n8k16.row.col.f32.bf16.bf16.f32 "           \
                 "{%0,%1,%2,%3}, {%4,%5,%6,%7}, {%8,%9}, {%0,%1,%2,%3};"          \
                 : "+f"((d)[0]), "+f"((d)[1]), "+f"((d)[2]), "+f"((d)[3])         \
                 : "r"((a)[0]), "r"((a)[1]), "r"((a)[2]), "r"((a)[3]),            \
                   "r"(b0v), "r"(b1v));

#define AS_STRIDE 20    // uint32 (bf16x2 pair) stride per A row: conflict-free frag loads
#define BS_STRIDE 136   // uint32 stride per B k-pair row:   136 mod 32 = 8 -> conflict-free

// ---------------- bf16x3 tensor-core GEMM: C = (A[M,K] @ B[K,128]) * rowscale[m]
// BM=128, BN=128, BK=32, 256 threads (8 warps, 4x2), warp tile 32x64, m16n8k16.
__global__ __launch_bounds__(256, 2)
void gemm_bf16_kernel(const float* __restrict__ A, const float* __restrict__ B,
                      const float* __restrict__ rowscale, float* __restrict__ C,
                      int M, int K) {
    __shared__ uint32_t As_hi[128 * AS_STRIDE];   // [row][kpair]
    __shared__ uint32_t As_lo[128 * AS_STRIDE];
    __shared__ uint32_t Bs_hi[16 * BS_STRIDE];    // [kpair][n]
    __shared__ uint32_t Bs_lo[16 * BS_STRIDE];

    const int tid  = threadIdx.x;
    const int warp = tid >> 5, lane = tid & 31;
    const int wm   = warp >> 1, wn = warp & 1;
    const int gid  = lane >> 2, tig = lane & 3;
    const int m0   = blockIdx.x * 128;

    float acc[2][8][4];
#pragma unroll
    for (int mt = 0; mt < 2; mt++)
#pragma unroll
        for (int nt = 0; nt < 8; nt++)
#pragma unroll
            for (int j = 0; j < 4; j++) acc[mt][nt][j] = 0.f;

    for (int k0 = 0; k0 < K; k0 += 32) {
        // ---- A tile 128x32 floats -> packed bf16x2 pairs (hi/lo) ----
#pragma unroll
        for (int l = 0; l < 4; l++) {
            int idx = tid + l * 256;              // 0..1023
            int r  = idx >> 3;                    // 8 float4 per row
            int c4 = idx & 7;                     // float4 index -> pairs 2c4, 2c4+1
            float4 v = make_float4(0.f, 0.f, 0.f, 0.f);
            if (m0 + r < M) v = *reinterpret_cast<const float4*>(A + (size_t)(m0 + r) * K + k0 + (c4 << 2));
            uint32_t h0, l0, h1, l1;
            split2_pack(v.x, v.y, h0, l0);
            split2_pack(v.z, v.w, h1, l1);
            As_hi[r * AS_STRIDE + 2 * c4]     = h0;
            As_hi[r * AS_STRIDE + 2 * c4 + 1] = h1;
            As_lo[r * AS_STRIDE + 2 * c4]     = l0;
            As_lo[r * AS_STRIDE + 2 * c4 + 1] = l1;
        }
        // ---- B tile 32x128 floats -> pair-packed [kp][n] (hi/lo) ----
#pragma unroll
        for (int l = 0; l < 8; l++) {
            int idx = tid + l * 256;              // 0..2047 : (kp, n)
            int n  = idx & 127;
            int kp = idx >> 7;                    // 0..15
            float x = B[(size_t)(k0 + 2 * kp)     * 128 + n];
            float y = B[(size_t)(k0 + 2 * kp + 1) * 128 + n];
            uint32_t h, lo;
            split2_pack(x, y, h, lo);
            Bs_hi[kp * BS_STRIDE + n] = h;
            Bs_lo[kp * BS_STRIDE + n] = lo;
        }
        __syncthreads();

#pragma unroll
        for (int kk = 0; kk < 32; kk += 16) {
            const int kkp = kk >> 1;              // k-pair base: 0 or 8
            uint32_t ah[2][4], al[2][4];
#pragma unroll
            for (int mt = 0; mt < 2; mt++) {
                int rb = wm * 32 + mt * 16 + gid;
                int p0 = kkp + tig;
                ah[mt][0] = As_hi[rb * AS_STRIDE + p0];
                ah[mt][1] = As_hi[(rb + 8) * AS_STRIDE + p0];
                ah[mt][2] = As_hi[rb * AS_STRIDE + p0 + 4];
                ah[mt][3] = As_hi[(rb + 8) * AS_STRIDE + p0 + 4];
                al[mt][0] = As_lo[rb * AS_STRIDE + p0];
                al[mt][1] = As_lo[(rb + 8) * AS_STRIDE + p0];
                al[mt][2] = As_lo[rb * AS_STRIDE + p0 + 4];
                al[mt][3] = As_lo[(rb + 8) * AS_STRIDE + p0 + 4];
            }
#pragma unroll
            for (int nt = 0; nt < 8; nt++) {
                int cb = wn * 64 + nt * 8 + gid;
                uint32_t bh0 = Bs_hi[(kkp + tig)     * BS_STRIDE + cb];
                uint32_t bh1 = Bs_hi[(kkp + tig + 4) * BS_STRIDE + cb];
                uint32_t bl0 = Bs_lo[(kkp + tig)     * BS_STRIDE + cb];
                uint32_t bl1 = Bs_lo[(kkp + tig + 4) * BS_STRIDE + cb];
#pragma unroll
                for (int mt = 0; mt < 2; mt++) {
                    MMA_BF16(acc[mt][nt], ah[mt], bh0, bh1);
                    MMA_BF16(acc[mt][nt], al[mt], bh0, bh1);
                    MMA_BF16(acc[mt][nt], ah[mt], bl0, bl1);
                }
            }
        }
        __syncthreads();
    }

    // epilogue: scale rows, store float2 pairs
#pragma unroll
    for (int mt = 0; mt < 2; mt++) {
        int r0 = m0 + wm * 32 + mt * 16 + gid;
        int r1 = r0 + 8;
        float s0 = (r0 < M) ? rowscale[r0] : 0.f;
        float s1 = (r1 < M) ? rowscale[r1] : 0.f;
#pragma unroll
        for (int nt = 0; nt < 8; nt++) {
            int c = wn * 64 + nt * 8 + 2 * tig;
            if (r0 < M) {
                float2 o = make_float2(acc[mt][nt][0] * s0, acc[mt][nt][1] * s0);
                *reinterpret_cast<float2*>(C + (size_t)r0 * 128 + c) = o;
            }
            if (r1 < M) {
                float2 o = make_float2(acc[mt][nt][2] * s1, acc[mt][nt][3] * s1);
                *reinterpret_cast<float2*>(C + (size_t)r1 * 128 + c) = o;
            }
        }
    }
}

// ---------------- CSR SpMM: out[v] = (sum_{s in N(v)} T[s]) * c_dst[v] + b  (optional relu)
__global__ void spmm_csr_kernel(const float* __restrict__ T, const int* __restrict__ csr,
                                const int* __restrict__ roff, const float* __restrict__ cdst,
                                const float* __restrict__ bias, float* __restrict__ out,
                                int n, int do_relu) {
    int w    = (blockIdx.x * blockDim.x + threadIdx.x) >> 5;
    int lane = threadIdx.x & 31;
    if (w >= n) return;
    int beg = __ldg(roff + w), end = __ldg(roff + w + 1);

    float4 acc = make_float4(0.f, 0.f, 0.f, 0.f);
    int i = beg;
    for (; i + 4 <= end; i += 4) {
        int s0 = __ldg(csr + i);
        int s1 = __ldg(csr + i + 1);
        int s2 = __ldg(csr + i + 2);
        int s3 = __ldg(csr + i + 3);
        float4 v0 = *reinterpret_cast<const float4*>(T + (size_t)s0 * 128 + (lane << 2));
        float4 v1 = *reinterpret_cast<const float4*>(T + (size_t)s1 * 128 + (lane << 2));
        float4 v2 = *reinterpret_cast<const float4*>(T + (size_t)s2 * 128 + (lane << 2));
        float4 v3 = *reinterpret_cast<const float4*>(T + (size_t)s3 * 128 + (lane << 2));
        acc.x += (v0.x + v1.x) + (v2.x + v3.x);
        acc.y += (v0.y + v1.y) + (v2.y + v3.y);
        acc.z += (v0.z + v1.z) + (v2.z + v3.z);
        acc.w += (v0.w + v1.w) + (v2.w + v3.w);
    }
    for (; i < end; i++) {
        int s = __ldg(csr + i);
        float4 v = *reinterpret_cast<const float4*>(T + (size_t)s * 128 + (lane << 2));
        acc.x += v.x; acc.y += v.y; acc.z += v.z; acc.w += v.w;
    }
    float c = __ldg(cdst + w);
    float4 b = *reinterpret_cast<const float4*>(bias + (lane << 2));
    acc.x = acc.x * c + b.x;
    acc.y = acc.y * c + b.y;
    acc.z = acc.z * c + b.z;
    acc.w = acc.w * c + b.w;
    if (do_relu) {
        acc.x = fmaxf(acc.x, 0.f); acc.y = fmaxf(acc.y, 0.f);
        acc.z = fmaxf(acc.z, 0.f); acc.w = fmaxf(acc.w, 0.f);
    }
    *reinterpret_cast<float4*>(out + (size_t)w * 128 + (lane << 2)) = acc;
}

// ---------------- final: logits = relu(h) @ Wc + bc  (h already in d_out) ----------------
__global__ void final_kernel(const float* __restrict__ h, const float* __restrict__ Wc,
                             const float* __restrict__ bc, float* __restrict__ out_logits, int n) {
    __shared__ float hs[32][HID + 1];
    __shared__ float Wcs[HID][CLS];
    __shared__ float bcs[CLS];

    const int tid = threadIdx.x;
    const int n0  = blockIdx.x * 32;

    for (int i = tid; i < HID * CLS; i += 256) Wcs[i / CLS][i % CLS] = Wc[i];
    if (tid < CLS) bcs[tid] = bc[tid];

    for (int i = tid; i < 32 * HID; i += 256) {
        int r = i >> 7, c = i & 127;
        int g = n0 + r;
        hs[r][c] = (g < n) ? fmaxf(h[(size_t)g * HID + c], 0.f) : 0.f;
    }
    __syncthreads();

    int r  = tid & 31;
    int cg = tid >> 5;
    int g  = n0 + r;
    if (g < n) {
        float acc[5];
#pragma unroll
        for (int j = 0; j < 5; j++) acc[j] = bcs[cg * 5 + j];
        for (int k = 0; k < HID; k++) {
            float a = hs[r][k];
#pragma unroll
            for (int j = 0; j < 5; j++) acc[j] = fmaf(a, Wcs[k][cg * 5 + j], acc[j]);
        }
#pragma unroll
        for (int j = 0; j < 5; j++) out_logits[(size_t)g * CLS + cg * 5 + j] = acc[j];
    }
}

// ---------------- launch ----------------
extern "C" void kernel_launch(void* const* d_in, const int* in_sizes, int n_in,
                              void* d_out, int out_size) {
    const float* x   = (const float*)d_in[0];
    const int*   src = (const int*)d_in[1];
    const int*   dst = (const int*)d_in[2];
    const float* W0  = (const float*)d_in[3];
    const float* b0  = (const float*)d_in[4];
    const float* W1  = (const float*)d_in[5];
    const float* b1  = (const float*)d_in[6];
    const float* Wc  = (const float*)d_in[7];
    const float* bc  = (const float*)d_in[8];

    const int n = in_sizes[0] / 256;   // IN_FEATS = 256
    const int e = in_sizes[1];

    int *ideg_s, *ideg_d, *roff, *cursor, *bsums, *csr;
    float *csrc, *cdst, *tmp, *hbuf;
    cudaGetSymbolAddress((void**)&ideg_s, g_ideg_src);
    cudaGetSymbolAddress((void**)&ideg_d, g_ideg_dst);
    cudaGetSymbolAddress((void**)&roff,   g_roff);
    cudaGetSymbolAddress((void**)&cursor, g_cursor);
    cudaGetSymbolAddress((void**)&bsums,  g_bsums);
    cudaGetSymbolAddress((void**)&csr,    g_csr);
    cudaGetSymbolAddress((void**)&csrc,   g_csrc);
    cudaGetSymbolAddress((void**)&cdst,   g_cdst);
    cudaGetSymbolAddress((void**)&tmp,    g_tmp);
    cudaGetSymbolAddress((void**)&hbuf,   g_hbuf);

    float* out_h      = (float*)d_out;
    float* out_logits = out_h + (size_t)n * HID;

    const int nb = (n + 1023) / 1024;

    zero_int2_kernel<<<(n + 255) / 256, 256>>>(ideg_s, ideg_d, n);
    degree_kernel<<<(e + 255) / 256, 256>>>(src, dst, e);

    scan1_kernel<<<nb, 1024>>>(ideg_d, roff, bsums, n);
    scan2_kernel<<<1, 128>>>(bsums, nb);
    scan3_kernel<<<(n + 255) / 256, 256>>>(roff, cursor, bsums, n, e);
    csr_fill_kernel<<<(e + 255) / 256, 256>>>(src, dst, cursor, csr, e);

    const int gblocks = (n + 127) / 128;
    const int sblocks = (int)(((size_t)n * 32 + 255) / 256);

    // layer 0
    gemm_bf16_kernel<<<gblocks, 256>>>(x, W0, csrc, tmp, n, 256);
    spmm_csr_kernel<<<sblocks, 256>>>(tmp, csr, roff, cdst, b0, hbuf, n, 1);

    // layer 1 (h written straight into d_out)
    gemm_bf16_kernel<<<gblocks, 256>>>(hbuf, W1, csrc, tmp, n, 128);
    spmm_csr_kernel<<<sblocks, 256>>>(tmp, csr, roff, cdst, b1, out_h, n, 0);

    // classifier head
    final_kernel<<<(n + 31) / 32, 256>>>(out_h, Wc, bc, out_logits, n);
}

// round 4
// speedup vs baseline: 3.2927x; 1.0240x over previous
#include <cuda_runtime.h>
#include <cuda_bf16.h>
#include <cstdint>

#define MAXN 100000
#define MAXE 1600000
#define HID 128
#define CLS 40

// ---------------- scratch (static device memory, no allocations) ----------------
__device__ int   g_ideg_src[MAXN];
__device__ int   g_ideg_dst[MAXN];
__device__ float g_csrc[MAXN];
__device__ float g_cdst[MAXN];
__device__ int   g_roff[MAXN + 1];
__device__ int   g_cursor[MAXN];
__device__ int   g_bsums[128];
__device__ int   g_csr[MAXE];
__device__ float g_tmp [(size_t)MAXN * HID];
__device__ float g_hbuf[(size_t)MAXN * HID];

// ---------------- utilities ----------------
__global__ void zero_int2_kernel(int* __restrict__ a, int* __restrict__ b, int n) {
    int i = blockIdx.x * blockDim.x + threadIdx.x;
    if (i < n) { a[i] = 0; b[i] = 0; }
}

__global__ void degree_kernel(const int* __restrict__ src, const int* __restrict__ dst, int e) {
    int i = blockIdx.x * blockDim.x + threadIdx.x;
    if (i < e) {
        atomicAdd(&g_ideg_src[src[i]], 1);
        atomicAdd(&g_ideg_dst[dst[i]], 1);
    }
}

// ---------------- 3-phase exclusive scan of in-degrees -> CSR row offsets ----------------
__global__ void scan1_kernel(const int* __restrict__ deg, int* __restrict__ out,
                             int* __restrict__ bsums, int n) {
    __shared__ int sm[1024];
    int i = blockIdx.x * 1024 + threadIdx.x;
    int v = (i < n) ? deg[i] : 0;
    sm[threadIdx.x] = v;
    __syncthreads();
    for (int off = 1; off < 1024; off <<= 1) {
        int t = (threadIdx.x >= off) ? sm[threadIdx.x - off] : 0;
        __syncthreads();
        sm[threadIdx.x] += t;
        __syncthreads();
    }
    if (i < n) out[i] = sm[threadIdx.x] - v;            // exclusive
    if (threadIdx.x == 1023) bsums[blockIdx.x] = sm[1023];
}

__global__ void scan2_kernel(int* __restrict__ bsums, int nb) {
    __shared__ int sm[128];
    int t = threadIdx.x;
    int v = (t < nb) ? bsums[t] : 0;
    sm[t] = v;
    __syncthreads();
    for (int off = 1; off < 128; off <<= 1) {
        int u = (t >= off) ? sm[t - off] : 0;
        __syncthreads();
        sm[t] += u;
        __syncthreads();
    }
    if (t < nb) bsums[t] = sm[t] - v;                   // exclusive
}

// scan3 + degree norms fused
__global__ void scan3_kernel(int* __restrict__ roff, int* __restrict__ cursor,
                             const int* __restrict__ bsums, int n, int e) {
    int i = blockIdx.x * blockDim.x + threadIdx.x;
    if (i < n) {
        int v = roff[i] + bsums[i >> 10];
        roff[i] = v;
        cursor[i] = v;
        g_csrc[i] = rsqrtf(fmaxf((float)g_ideg_src[i], 1.f));
        g_cdst[i] = rsqrtf(fmaxf((float)g_ideg_dst[i], 1.f));
    }
    if (i == 0) roff[n] = e;
}

__global__ void csr_fill_kernel(const int* __restrict__ src, const int* __restrict__ dst,
                                int* __restrict__ cursor, int* __restrict__ csr, int e) {
    int i = blockIdx.x * blockDim.x + threadIdx.x;
    if (i < e) {
        int d = dst[i];
        int pos = atomicAdd(&cursor[d], 1);
        csr[pos] = src[i];
    }
}

// ---------------- bf16 split helpers ----------------
__device__ __forceinline__ void split2_pack(float x, float y, uint32_t& hi, uint32_t& lo) {
    __nv_bfloat16 hx = __float2bfloat16(x);
    __nv_bfloat16 hy = __float2bfloat16(y);
    float rx = x - __bfloat162float(hx);
    float ry = y - __bfloat162float(hy);
    __nv_bfloat162 h2 = __halves2bfloat162(hx, hy);
    __nv_bfloat162 l2 = __floats2bfloat162_rn(rx, ry);
    hi = *reinterpret_cast<uint32_t*>(&h2);
    lo = *reinterpret_cast<uint32_t*>(&l2);
}

#define MMA_BF16(d, a, b0v, b1v)                                                  \
    asm volatile("mma.sync.aligned.m16n8k16.row.col.f32.bf16.bf16.f32 "           \
                 "{%0,%1,%2,%3}, {%4,%5,%6,%7}, {%8,%9}, {%0,%1,%2,%3};"          \
                 : "+f"((d)[0]), "+f"((d)[1]), "+f"((d)[2]), "+f"((d)[3])         \
                 : "r"((a)[0]), "r"((a)[1]), "r"((a)[2]), "r"((a)[3]),            \
                   "r"(b0v), "r"(b1v));

#define AS_STRIDE 20    // uint32 (bf16x2 pair) stride per A row
#define BS_STRIDE 136   // uint32 stride per B k-pair row

// ---------------- bf16x3 tensor-core GEMM: C = A[M,K] @ B[K,128]  (no row scale)
// BM=128, BN=128, BK=32, 256 threads (8 warps, 4x2), warp tile 32x64, m16n8k16.
__global__ __launch_bounds__(256, 2)
void gemm_bf16_kernel(const float* __restrict__ A, const float* __restrict__ B,
                      float* __restrict__ C, int M, int K) {
    __shared__ uint32_t As_hi[128 * AS_STRIDE];   // [row][kpair]
    __shared__ uint32_t As_lo[128 * AS_STRIDE];
    __shared__ uint32_t Bs_hi[16 * BS_STRIDE];    // [kpair][n]
    __shared__ uint32_t Bs_lo[16 * BS_STRIDE];

    const int tid  = threadIdx.x;
    const int warp = tid >> 5, lane = tid & 31;
    const int wm   = warp >> 1, wn = warp & 1;
    const int gid  = lane >> 2, tig = lane & 3;
    const int m0   = blockIdx.x * 128;

    float acc[2][8][4];
#pragma unroll
    for (int mt = 0; mt < 2; mt++)
#pragma unroll
        for (int nt = 0; nt < 8; nt++)
#pragma unroll
            for (int j = 0; j < 4; j++) acc[mt][nt][j] = 0.f;

    for (int k0 = 0; k0 < K; k0 += 32) {
        // ---- A tile 128x32 floats -> packed bf16x2 pairs (hi/lo) ----
#pragma unroll
        for (int l = 0; l < 4; l++) {
            int idx = tid + l * 256;              // 0..1023
            int r  = idx >> 3;
            int c4 = idx & 7;
            float4 v = make_float4(0.f, 0.f, 0.f, 0.f);
            if (m0 + r < M) v = *reinterpret_cast<const float4*>(A + (size_t)(m0 + r) * K + k0 + (c4 << 2));
            uint32_t h0, l0, h1, l1;
            split2_pack(v.x, v.y, h0, l0);
            split2_pack(v.z, v.w, h1, l1);
            As_hi[r * AS_STRIDE + 2 * c4]     = h0;
            As_hi[r * AS_STRIDE + 2 * c4 + 1] = h1;
            As_lo[r * AS_STRIDE + 2 * c4]     = l0;
            As_lo[r * AS_STRIDE + 2 * c4 + 1] = l1;
        }
        // ---- B tile 32x128 floats -> pair-packed [kp][n] (hi/lo) ----
#pragma unroll
        for (int l = 0; l < 8; l++) {
            int idx = tid + l * 256;              // 0..2047 : (kp, n)
            int n  = idx & 127;
            int kp = idx >> 7;                    // 0..15
            float x = B[(size_t)(k0 + 2 * kp)     * 128 + n];
            float y = B[(size_t)(k0 + 2 * kp + 1) * 128 + n];
            uint32_t h, lo;
            split2_pack(x, y, h, lo);
            Bs_hi[kp * BS_STRIDE + n] = h;
            Bs_lo[kp * BS_STRIDE + n] = lo;
        }
        __syncthreads();

#pragma unroll
        for (int kk = 0; kk < 32; kk += 16) {
            const int kkp = kk >> 1;
            uint32_t ah[2][4], al[2][4];
#pragma unroll
            for (int mt = 0; mt < 2; mt++) {
                int rb = wm * 32 + mt * 16 + gid;
                int p0 = kkp + tig;
                ah[mt][0] = As_hi[rb * AS_STRIDE + p0];
                ah[mt][1] = As_hi[(rb + 8) * AS_STRIDE + p0];
                ah[mt][2] = As_hi[rb * AS_STRIDE + p0 + 4];
                ah[mt][3] = As_hi[(rb + 8) * AS_STRIDE + p0 + 4];
                al[mt][0] = As_lo[rb * AS_STRIDE + p0];
                al[mt][1] = As_lo[(rb + 8) * AS_STRIDE + p0];
                al[mt][2] = As_lo[rb * AS_STRIDE + p0 + 4];
                al[mt][3] = As_lo[(rb + 8) * AS_STRIDE + p0 + 4];
            }
#pragma unroll
            for (int nt = 0; nt < 8; nt++) {
                int cb = wn * 64 + nt * 8 + gid;
                uint32_t bh0 = Bs_hi[(kkp + tig)     * BS_STRIDE + cb];
                uint32_t bh1 = Bs_hi[(kkp + tig + 4) * BS_STRIDE + cb];
                uint32_t bl0 = Bs_lo[(kkp + tig)     * BS_STRIDE + cb];
                uint32_t bl1 = Bs_lo[(kkp + tig + 4) * BS_STRIDE + cb];
#pragma unroll
                for (int mt = 0; mt < 2; mt++) {
                    MMA_BF16(acc[mt][nt], ah[mt], bh0, bh1);
                    MMA_BF16(acc[mt][nt], al[mt], bh0, bh1);
                    MMA_BF16(acc[mt][nt], ah[mt], bl0, bl1);
                }
            }
        }
        __syncthreads();
    }

    // epilogue: store float2 pairs (no scaling — c_src applied in SpMM gather)
#pragma unroll
    for (int mt = 0; mt < 2; mt++) {
        int r0 = m0 + wm * 32 + mt * 16 + gid;
        int r1 = r0 + 8;
#pragma unroll
        for (int nt = 0; nt < 8; nt++) {
            int c = wn * 64 + nt * 8 + 2 * tig;
            if (r0 < M) {
                float2 o = make_float2(acc[mt][nt][0], acc[mt][nt][1]);
                *reinterpret_cast<float2*>(C + (size_t)r0 * 128 + c) = o;
            }
            if (r1 < M) {
                float2 o = make_float2(acc[mt][nt][2], acc[mt][nt][3]);
                *reinterpret_cast<float2*>(C + (size_t)r1 * 128 + c) = o;
            }
        }
    }
}

// ---------------- CSR SpMM: out[v] = (sum_{s in N(v)} c_src[s]*T[s]) * c_dst[v] + b  (optional relu)
__global__ void spmm_csr_kernel(const float* __restrict__ T, const int* __restrict__ csr,
                                const int* __restrict__ roff, const float* __restrict__ csrc,
                                const float* __restrict__ cdst,
                                const float* __restrict__ bias, float* __restrict__ out,
                                int n, int do_relu) {
    int w    = (blockIdx.x * blockDim.x + threadIdx.x) >> 5;
    int lane = threadIdx.x & 31;
    if (w >= n) return;
    int beg = __ldg(roff + w), end = __ldg(roff + w + 1);

    float4 acc = make_float4(0.f, 0.f, 0.f, 0.f);
    int i = beg;
    for (; i + 4 <= end; i += 4) {
        int s0 = __ldg(csr + i);
        int s1 = __ldg(csr + i + 1);
        int s2 = __ldg(csr + i + 2);
        int s3 = __ldg(csr + i + 3);
        float c0 = __ldg(csrc + s0);
        float c1 = __ldg(csrc + s1);
        float c2 = __ldg(csrc + s2);
        float c3 = __ldg(csrc + s3);
        float4 v0 = *reinterpret_cast<const float4*>(T + (size_t)s0 * 128 + (lane << 2));
        float4 v1 = *reinterpret_cast<const float4*>(T + (size_t)s1 * 128 + (lane << 2));
        float4 v2 = *reinterpret_cast<const float4*>(T + (size_t)s2 * 128 + (lane << 2));
        float4 v3 = *reinterpret_cast<const float4*>(T + (size_t)s3 * 128 + (lane << 2));
        acc.x += (v0.x * c0 + v1.x * c1) + (v2.x * c2 + v3.x * c3);
        acc.y += (v0.y * c0 + v1.y * c1) + (v2.y * c2 + v3.y * c3);
        acc.z += (v0.z * c0 + v1.z * c1) + (v2.z * c2 + v3.z * c3);
        acc.w += (v0.w * c0 + v1.w * c1) + (v2.w * c2 + v3.w * c3);
    }
    for (; i < end; i++) {
        int s = __ldg(csr + i);
        float c = __ldg(csrc + s);
        float4 v = *reinterpret_cast<const float4*>(T + (size_t)s * 128 + (lane << 2));
        acc.x += v.x * c; acc.y += v.y * c; acc.z += v.z * c; acc.w += v.w * c;
    }
    float c = __ldg(cdst + w);
    float4 b = *reinterpret_cast<const float4*>(bias + (lane << 2));
    acc.x = acc.x * c + b.x;
    acc.y = acc.y * c + b.y;
    acc.z = acc.z * c + b.z;
    acc.w = acc.w * c + b.w;
    if (do_relu) {
        acc.x = fmaxf(acc.x, 0.f); acc.y = fmaxf(acc.y, 0.f);
        acc.z = fmaxf(acc.z, 0.f); acc.w = fmaxf(acc.w, 0.f);
    }
    *reinterpret_cast<float4*>(out + (size_t)w * 128 + (lane << 2)) = acc;
}

// ---------------- final: logits = relu(h) @ Wc + bc  (h already in d_out) ----------------
__global__ void final_kernel(const float* __restrict__ h, const float* __restrict__ Wc,
                             const float* __restrict__ bc, float* __restrict__ out_logits, int n) {
    __shared__ float hs[32][HID + 1];
    __shared__ float Wcs[HID][CLS];
    __shared__ float bcs[CLS];

    const int tid = threadIdx.x;
    const int n0  = blockIdx.x * 32;

    for (int i = tid; i < HID * CLS; i += 256) Wcs[i / CLS][i % CLS] = Wc[i];
    if (tid < CLS) bcs[tid] = bc[tid];

    for (int i = tid; i < 32 * HID; i += 256) {
        int r = i >> 7, c = i & 127;
        int g = n0 + r;
        hs[r][c] = (g < n) ? fmaxf(h[(size_t)g * HID + c], 0.f) : 0.f;
    }
    __syncthreads();

    int r  = tid & 31;
    int cg = tid >> 5;
    int g  = n0 + r;
    if (g < n) {
        float acc[5];
#pragma unroll
        for (int j = 0; j < 5; j++) acc[j] = bcs[cg * 5 + j];
        for (int k = 0; k < HID; k++) {
            float a = hs[r][k];
#pragma unroll
            for (int j = 0; j < 5; j++) acc[j] = fmaf(a, Wcs[k][cg * 5 + j], acc[j]);
        }
#pragma unroll
        for (int j = 0; j < 5; j++) out_logits[(size_t)g * CLS + cg * 5 + j] = acc[j];
    }
}

// ---------------- launch ----------------
extern "C" void kernel_launch(void* const* d_in, const int* in_sizes, int n_in,
                              void* d_out, int out_size) {
    const float* x   = (const float*)d_in[0];
    const int*   src = (const int*)d_in[1];
    const int*   dst = (const int*)d_in[2];
    const float* W0  = (const float*)d_in[3];
    const float* b0  = (const float*)d_in[4];
    const float* W1  = (const float*)d_in[5];
    const float* b1  = (const float*)d_in[6];
    const float* Wc  = (const float*)d_in[7];
    const float* bc  = (const float*)d_in[8];

    const int n = in_sizes[0] / 256;   // IN_FEATS = 256
    const int e = in_sizes[1];

    int *ideg_s, *ideg_d, *roff, *cursor, *bsums, *csr;
    float *csrc, *cdst, *tmp, *hbuf;
    cudaGetSymbolAddress((void**)&ideg_s, g_ideg_src);
    cudaGetSymbolAddress((void**)&ideg_d, g_ideg_dst);
    cudaGetSymbolAddress((void**)&roff,   g_roff);
    cudaGetSymbolAddress((void**)&cursor, g_cursor);
    cudaGetSymbolAddress((void**)&bsums,  g_bsums);
    cudaGetSymbolAddress((void**)&csr,    g_csr);
    cudaGetSymbolAddress((void**)&csrc,   g_csrc);
    cudaGetSymbolAddress((void**)&cdst,   g_cdst);
    cudaGetSymbolAddress((void**)&tmp,    g_tmp);
    cudaGetSymbolAddress((void**)&hbuf,   g_hbuf);

    float* out_h      = (float*)d_out;
    float* out_logits = out_h + (size_t)n * HID;

    // one-time stream/event setup (host resources, not device memory;
    // per-call launched work is identical on every call)
    static cudaStream_t s_side = nullptr;
    static cudaEvent_t  ev_fork = nullptr, ev_join = nullptr;
    if (s_side == nullptr) {
        cudaStreamCreateWithFlags(&s_side, cudaStreamNonBlocking);
        cudaEventCreateWithFlags(&ev_fork, cudaEventDisableTiming);
        cudaEventCreateWithFlags(&ev_join, cudaEventDisableTiming);
    }

    const int nb = (n + 1023) / 1024;
    const int gblocks = (n + 127) / 128;
    const int sblocks = (int)(((size_t)n * 32 + 255) / 256);

    // ---- fork: CSR/degree chain on side stream, GEMM1 on main stream ----
    cudaEventRecord(ev_fork, 0);
    cudaStreamWaitEvent(s_side, ev_fork, 0);

    zero_int2_kernel<<<(n + 255) / 256, 256, 0, s_side>>>(ideg_s, ideg_d, n);
    degree_kernel<<<(e + 255) / 256, 256, 0, s_side>>>(src, dst, e);
    scan1_kernel<<<nb, 1024, 0, s_side>>>(ideg_d, roff, bsums, n);
    scan2_kernel<<<1, 128, 0, s_side>>>(bsums, nb);
    scan3_kernel<<<(n + 255) / 256, 256, 0, s_side>>>(roff, cursor, bsums, n, e);
    csr_fill_kernel<<<(e + 255) / 256, 256, 0, s_side>>>(src, dst, cursor, csr, e);

    gemm_bf16_kernel<<<gblocks, 256>>>(x, W0, tmp, n, 256);   // graph-independent now

    // ---- join ----
    cudaEventRecord(ev_join, s_side);
    cudaStreamWaitEvent(0, ev_join, 0);

    // layer 0 aggregate (+bias+relu)
    spmm_csr_kernel<<<sblocks, 256>>>(tmp, csr, roff, csrc, cdst, b0, hbuf, n, 1);

    // layer 1
    gemm_bf16_kernel<<<gblocks, 256>>>(hbuf, W1, tmp, n, 128);
    spmm_csr_kernel<<<sblocks, 256>>>(tmp, csr, roff, csrc, cdst, b1, out_h, n, 0);

    // classifier head
    final_kernel<<<(n + 31) / 32, 256>>>(out_h, Wc, bc, out_logits, n);
}

// round 5
// speedup vs baseline: 3.6509x; 1.1088x over previous
#include <cuda_runtime.h>
#include <cuda_bf16.h>
#include <cuda_fp16.h>
#include <cstdint>

#define MAXN 100000
#define MAXE 1600000
#define HID 128
#define CLS 40

// ---------------- scratch (static device memory, no allocations) ----------------
__device__ int      g_ideg_src[MAXN];
__device__ int      g_ideg_dst[MAXN];
__device__ float    g_csrc[MAXN];
__device__ float    g_cdst[MAXN];
__device__ int      g_roff[MAXN + 1];
__device__ int      g_cursor[MAXN];
__device__ int      g_bsums[128];
__device__ int      g_csr[MAXE];
__device__ __half   g_tmp [(size_t)MAXN * HID];     // GEMM output, fp16
__device__ float    g_hbuf[(size_t)MAXN * HID];
__device__ uint32_t g_whi[16384];                   // pre-split weights (K/2 x 128 bf16x2)
__device__ uint32_t g_wlo[16384];

// ---------------- utilities ----------------
__global__ void zero_int2_kernel(int* __restrict__ a, int* __restrict__ b, int n) {
    int i = blockIdx.x * blockDim.x + threadIdx.x;
    if (i < n) { a[i] = 0; b[i] = 0; }
}

__global__ void degree_kernel(const int* __restrict__ src, const int* __restrict__ dst, int e) {
    int i = blockIdx.x * blockDim.x + threadIdx.x;
    if (i < e) {
        atomicAdd(&g_ideg_src[src[i]], 1);
        atomicAdd(&g_ideg_dst[dst[i]], 1);
    }
}

// ---------------- 3-phase exclusive scan of in-degrees -> CSR row offsets ----------------
__global__ void scan1_kernel(const int* __restrict__ deg, int* __restrict__ out,
                             int* __restrict__ bsums, int n) {
    __shared__ int sm[1024];
    int i = blockIdx.x * 1024 + threadIdx.x;
    int v = (i < n) ? deg[i] : 0;
    sm[threadIdx.x] = v;
    __syncthreads();
    for (int off = 1; off < 1024; off <<= 1) {
        int t = (threadIdx.x >= off) ? sm[threadIdx.x - off] : 0;
        __syncthreads();
        sm[threadIdx.x] += t;
        __syncthreads();
    }
    if (i < n) out[i] = sm[threadIdx.x] - v;
    if (threadIdx.x == 1023) bsums[blockIdx.x] = sm[1023];
}

__global__ void scan2_kernel(int* __restrict__ bsums, int nb) {
    __shared__ int sm[128];
    int t = threadIdx.x;
    int v = (t < nb) ? bsums[t] : 0;
    sm[t] = v;
    __syncthreads();
    for (int off = 1; off < 128; off <<= 1) {
        int u = (t >= off) ? sm[t - off] : 0;
        __syncthreads();
        sm[t] += u;
        __syncthreads();
    }
    if (t < nb) bsums[t] = sm[t] - v;
}

__global__ void scan3_kernel(int* __restrict__ roff, int* __restrict__ cursor,
                             const int* __restrict__ bsums, int n, int e) {
    int i = blockIdx.x * blockDim.x + threadIdx.x;
    if (i < n) {
        int v = roff[i] + bsums[i >> 10];
        roff[i] = v;
        cursor[i] = v;
        g_csrc[i] = rsqrtf(fmaxf((float)g_ideg_src[i], 1.f));
        g_cdst[i] = rsqrtf(fmaxf((float)g_ideg_dst[i], 1.f));
    }
    if (i == 0) roff[n] = e;
}

__global__ void csr_fill_kernel(const int* __restrict__ src, const int* __restrict__ dst,
                                int* __restrict__ cursor, int* __restrict__ csr, int e) {
    int i = blockIdx.x * blockDim.x + threadIdx.x;
    if (i < e) {
        int d = dst[i];
        int pos = atomicAdd(&cursor[d], 1);
        csr[pos] = src[i];
    }
}

// ---------------- bf16 split helpers ----------------
__device__ __forceinline__ void split2_pack(float x, float y, uint32_t& hi, uint32_t& lo) {
    __nv_bfloat16 hx = __float2bfloat16(x);
    __nv_bfloat16 hy = __float2bfloat16(y);
    float rx = x - __bfloat162float(hx);
    float ry = y - __bfloat162float(hy);
    __nv_bfloat162 h2 = __halves2bfloat162(hx, hy);
    __nv_bfloat162 l2 = __floats2bfloat162_rn(rx, ry);
    hi = *reinterpret_cast<uint32_t*>(&h2);
    lo = *reinterpret_cast<uint32_t*>(&l2);
}

// pre-split weights: W[K,128] fp32 -> [K/2][128] bf16x2 hi/lo
__global__ void wsplit_kernel(const float* __restrict__ W, int kpairs) {
    int idx = blockIdx.x * blockDim.x + threadIdx.x;     // (kp, n)
    if (idx < kpairs * 128) {
        int kp = idx >> 7, n = idx & 127;
        float x = W[(size_t)(2 * kp) * 128 + n];
        float y = W[(size_t)(2 * kp + 1) * 128 + n];
        uint32_t h, l;
        split2_pack(x, y, h, l);
        g_whi[idx] = h;
        g_wlo[idx] = l;
    }
}

#define MMA_BF16(d, a, b0v, b1v)                                                  \
    asm volatile("mma.sync.aligned.m16n8k16.row.col.f32.bf16.bf16.f32 "           \
                 "{%0,%1,%2,%3}, {%4,%5,%6,%7}, {%8,%9}, {%0,%1,%2,%3};"          \
                 : "+f"((d)[0]), "+f"((d)[1]), "+f"((d)[2]), "+f"((d)[3])         \
                 : "r"((a)[0]), "r"((a)[1]), "r"((a)[2]), "r"((a)[3]),            \
                   "r"(b0v), "r"(b1v));

#define AS_STRIDE 20
#define BS_STRIDE 136

// ---------------- bf16x3 tensor-core GEMM: C(fp16) = A[M,K](fp32) @ Wsplit[K,128]
__global__ __launch_bounds__(256, 2)
void gemm_bf16_kernel(const float* __restrict__ A, __half* __restrict__ C, int M, int K) {
    __shared__ uint32_t As_hi[128 * AS_STRIDE];
    __shared__ uint32_t As_lo[128 * AS_STRIDE];
    __shared__ uint32_t Bs_hi[16 * BS_STRIDE];
    __shared__ uint32_t Bs_lo[16 * BS_STRIDE];

    const int tid  = threadIdx.x;
    const int warp = tid >> 5, lane = tid & 31;
    const int wm   = warp >> 1, wn = warp & 1;
    const int gid  = lane >> 2, tig = lane & 3;
    const int m0   = blockIdx.x * 128;

    float acc[2][8][4];
#pragma unroll
    for (int mt = 0; mt < 2; mt++)
#pragma unroll
        for (int nt = 0; nt < 8; nt++)
#pragma unroll
            for (int j = 0; j < 4; j++) acc[mt][nt][j] = 0.f;

    for (int k0 = 0; k0 < K; k0 += 32) {
        const int k0p = k0 >> 1;
        // ---- A tile 128x32 floats -> packed bf16x2 pairs (hi/lo) ----
#pragma unroll
        for (int l = 0; l < 4; l++) {
            int idx = tid + l * 256;
            int r  = idx >> 3;
            int c4 = idx & 7;
            float4 v = make_float4(0.f, 0.f, 0.f, 0.f);
            if (m0 + r < M) v = *reinterpret_cast<const float4*>(A + (size_t)(m0 + r) * K + k0 + (c4 << 2));
            uint32_t h0, l0, h1, l1;
            split2_pack(v.x, v.y, h0, l0);
            split2_pack(v.z, v.w, h1, l1);
            As_hi[r * AS_STRIDE + 2 * c4]     = h0;
            As_hi[r * AS_STRIDE + 2 * c4 + 1] = h1;
            As_lo[r * AS_STRIDE + 2 * c4]     = l0;
            As_lo[r * AS_STRIDE + 2 * c4 + 1] = l1;
        }
        // ---- B tile: copy pre-split weights [kp][n] ----
#pragma unroll
        for (int l = 0; l < 8; l++) {
            int idx = tid + l * 256;              // 0..2047 : (kp, n)
            int n  = idx & 127;
            int kp = idx >> 7;
            Bs_hi[kp * BS_STRIDE + n] = g_whi[(k0p + kp) * 128 + n];
            Bs_lo[kp * BS_STRIDE + n] = g_wlo[(k0p + kp) * 128 + n];
        }
        __syncthreads();

#pragma unroll
        for (int kk = 0; kk < 32; kk += 16) {
            const int kkp = kk >> 1;
            uint32_t ah[2][4], al[2][4];
#pragma unroll
            for (int mt = 0; mt < 2; mt++) {
                int rb = wm * 32 + mt * 16 + gid;
                int p0 = kkp + tig;
                ah[mt][0] = As_hi[rb * AS_STRIDE + p0];
                ah[mt][1] = As_hi[(rb + 8) * AS_STRIDE + p0];
                ah[mt][2] = As_hi[rb * AS_STRIDE + p0 + 4];
                ah[mt][3] = As_hi[(rb + 8) * AS_STRIDE + p0 + 4];
                al[mt][0] = As_lo[rb * AS_STRIDE + p0];
                al[mt][1] = As_lo[(rb + 8) * AS_STRIDE + p0];
                al[mt][2] = As_lo[rb * AS_STRIDE + p0 + 4];
                al[mt][3] = As_lo[(rb + 8) * AS_STRIDE + p0 + 4];
            }
#pragma unroll
            for (int nt = 0; nt < 8; nt++) {
                int cb = wn * 64 + nt * 8 + gid;
                uint32_t bh0 = Bs_hi[(kkp + tig)     * BS_STRIDE + cb];
                uint32_t bh1 = Bs_hi[(kkp + tig + 4) * BS_STRIDE + cb];
                uint32_t bl0 = Bs_lo[(kkp + tig)     * BS_STRIDE + cb];
                uint32_t bl1 = Bs_lo[(kkp + tig + 4) * BS_STRIDE + cb];
#pragma unroll
                for (int mt = 0; mt < 2; mt++) {
                    MMA_BF16(acc[mt][nt], ah[mt], bh0, bh1);
                    MMA_BF16(acc[mt][nt], al[mt], bh0, bh1);
                    MMA_BF16(acc[mt][nt], ah[mt], bl0, bl1);
                }
            }
        }
        __syncthreads();
    }

    // epilogue: store fp16 pairs (c_src applied later in SpMM gather)
#pragma unroll
    for (int mt = 0; mt < 2; mt++) {
        int r0 = m0 + wm * 32 + mt * 16 + gid;
        int r1 = r0 + 8;
#pragma unroll
        for (int nt = 0; nt < 8; nt++) {
            int c = wn * 64 + nt * 8 + 2 * tig;
            if (r0 < M) {
                __half2 o = __floats2half2_rn(acc[mt][nt][0], acc[mt][nt][1]);
                *reinterpret_cast<__half2*>(C + (size_t)r0 * 128 + c) = o;
            }
            if (r1 < M) {
                __half2 o = __floats2half2_rn(acc[mt][nt][2], acc[mt][nt][3]);
                *reinterpret_cast<__half2*>(C + (size_t)r1 * 128 + c) = o;
            }
        }
    }
}

// ---------------- CSR SpMM (fp16 gather, fp32 accum):
// out[v] = (sum_{s in N(v)} c_src[s]*T[s]) * c_dst[v] + b   (optional relu)
__global__ void spmm_csr_kernel(const __half* __restrict__ T, const int* __restrict__ csr,
                                const int* __restrict__ roff, const float* __restrict__ csrc,
                                const float* __restrict__ cdst,
                                const float* __restrict__ bias, float* __restrict__ out,
                                int n, int do_relu) {
    int w    = (blockIdx.x * blockDim.x + threadIdx.x) >> 5;
    int lane = threadIdx.x & 31;
    if (w >= n) return;
    int beg = __ldg(roff + w), end = __ldg(roff + w + 1);

    float4 acc = make_float4(0.f, 0.f, 0.f, 0.f);
    int i = beg;
    for (; i + 4 <= end; i += 4) {
        int s0 = __ldg(csr + i);
        int s1 = __ldg(csr + i + 1);
        int s2 = __ldg(csr + i + 2);
        int s3 = __ldg(csr + i + 3);
        float c0 = __ldg(csrc + s0);
        float c1 = __ldg(csrc + s1);
        float c2 = __ldg(csrc + s2);
        float c3 = __ldg(csrc + s3);
        uint2 u0 = *(reinterpret_cast<const uint2*>(T + (size_t)s0 * 128) + lane);
        uint2 u1 = *(reinterpret_cast<const uint2*>(T + (size_t)s1 * 128) + lane);
        uint2 u2 = *(reinterpret_cast<const uint2*>(T + (size_t)s2 * 128) + lane);
        uint2 u3 = *(reinterpret_cast<const uint2*>(T + (size_t)s3 * 128) + lane);
        float2 a0 = __half22float2(*reinterpret_cast<__half2*>(&u0.x));
        float2 b0v = __half22float2(*reinterpret_cast<__half2*>(&u0.y));
        float2 a1 = __half22float2(*reinterpret_cast<__half2*>(&u1.x));
        float2 b1v = __half22float2(*reinterpret_cast<__half2*>(&u1.y));
        float2 a2 = __half22float2(*reinterpret_cast<__half2*>(&u2.x));
        float2 b2v = __half22float2(*reinterpret_cast<__half2*>(&u2.y));
        float2 a3 = __half22float2(*reinterpret_cast<__half2*>(&u3.x));
        float2 b3v = __half22float2(*reinterpret_cast<__half2*>(&u3.y));
        acc.x += (a0.x * c0 + a1.x * c1) + (a2.x * c2 + a3.x * c3);
        acc.y += (a0.y * c0 + a1.y * c1) + (a2.y * c2 + a3.y * c3);
        acc.z += (b0v.x * c0 + b1v.x * c1) + (b2v.x * c2 + b3v.x * c3);
        acc.w += (b0v.y * c0 + b1v.y * c1) + (b2v.y * c2 + b3v.y * c3);
    }
    for (; i < end; i++) {
        int s = __ldg(csr + i);
        float c = __ldg(csrc + s);
        uint2 u = *(reinterpret_cast<const uint2*>(T + (size_t)s * 128) + lane);
        float2 a = __half22float2(*reinterpret_cast<__half2*>(&u.x));
        float2 b = __half22float2(*reinterpret_cast<__half2*>(&u.y));
        acc.x += a.x * c; acc.y += a.y * c; acc.z += b.x * c; acc.w += b.y * c;
    }
    float c = __ldg(cdst + w);
    // lane covers 4 consecutive features at 4*lane
    float4 b = *reinterpret_cast<const float4*>(bias + (lane << 2));
    acc.x = acc.x * c + b.x;
    acc.y = acc.y * c + b.y;
    acc.z = acc.z * c + b.z;
    acc.w = acc.w * c + b.w;
    if (do_relu) {
        acc.x = fmaxf(acc.x, 0.f); acc.y = fmaxf(acc.y, 0.f);
        acc.z = fmaxf(acc.z, 0.f); acc.w = fmaxf(acc.w, 0.f);
    }
    *reinterpret_cast<float4*>(out + (size_t)w * 128 + (lane << 2)) = acc;
}

// ---------------- final: logits = relu(h) @ Wc + bc ----------------
__global__ void final_kernel(const float* __restrict__ h, const float* __restrict__ Wc,
                             const float* __restrict__ bc, float* __restrict__ out_logits, int n) {
    __shared__ float hs[32][HID + 1];
    __shared__ float Wcs[HID][CLS];
    __shared__ float bcs[CLS];

    const int tid = threadIdx.x;
    const int n0  = blockIdx.x * 32;

    for (int i = tid; i < HID * CLS; i += 256) Wcs[i / CLS][i % CLS] = Wc[i];
    if (tid < CLS) bcs[tid] = bc[tid];

    for (int i = tid; i < 32 * HID; i += 256) {
        int r = i >> 7, c = i & 127;
        int g = n0 + r;
        hs[r][c] = (g < n) ? fmaxf(h[(size_t)g * HID + c], 0.f) : 0.f;
    }
    __syncthreads();

    int r  = tid & 31;
    int cg = tid >> 5;
    int g  = n0 + r;
    if (g < n) {
        float acc[5];
#pragma unroll
        for (int j = 0; j < 5; j++) acc[j] = bcs[cg * 5 + j];
        for (int k = 0; k < HID; k++) {
            float a = hs[r][k];
#pragma unroll
            for (int j = 0; j < 5; j++) acc[j] = fmaf(a, Wcs[k][cg * 5 + j], acc[j]);
        }
#pragma unroll
        for (int j = 0; j < 5; j++) out_logits[(size_t)g * CLS + cg * 5 + j] = acc[j];
    }
}

// ---------------- launch ----------------
extern "C" void kernel_launch(void* const* d_in, const int* in_sizes, int n_in,
                              void* d_out, int out_size) {
    const float* x   = (const float*)d_in[0];
    const int*   src = (const int*)d_in[1];
    const int*   dst = (const int*)d_in[2];
    const float* W0  = (const float*)d_in[3];
    const float* b0  = (const float*)d_in[4];
    const float* W1  = (const float*)d_in[5];
    const float* b1  = (const float*)d_in[6];
    const float* Wc  = (const float*)d_in[7];
    const float* bc  = (const float*)d_in[8];

    const int n = in_sizes[0] / 256;
    const int e = in_sizes[1];

    int *ideg_s, *ideg_d, *roff, *cursor, *bsums, *csr;
    float *csrc, *cdst, *hbuf;
    __half* tmp;
    cudaGetSymbolAddress((void**)&ideg_s, g_ideg_src);
    cudaGetSymbolAddress((void**)&ideg_d, g_ideg_dst);
    cudaGetSymbolAddress((void**)&roff,   g_roff);
    cudaGetSymbolAddress((void**)&cursor, g_cursor);
    cudaGetSymbolAddress((void**)&bsums,  g_bsums);
    cudaGetSymbolAddress((void**)&csr,    g_csr);
    cudaGetSymbolAddress((void**)&csrc,   g_csrc);
    cudaGetSymbolAddress((void**)&cdst,   g_cdst);
    cudaGetSymbolAddress((void**)&tmp,    g_tmp);
    cudaGetSymbolAddress((void**)&hbuf,   g_hbuf);

    float* out_h      = (float*)d_out;
    float* out_logits = out_h + (size_t)n * HID;

    static cudaStream_t s_side = nullptr;
    static cudaEvent_t  ev_fork = nullptr, ev_join = nullptr;
    if (s_side == nullptr) {
        cudaStreamCreateWithFlags(&s_side, cudaStreamNonBlocking);
        cudaEventCreateWithFlags(&ev_fork, cudaEventDisableTiming);
        cudaEventCreateWithFlags(&ev_join, cudaEventDisableTiming);
    }

    const int nb = (n + 1023) / 1024;
    const int gblocks = (n + 127) / 128;
    const int sblocks = (int)(((size_t)n * 32 + 255) / 256);

    // ---- fork: CSR/degree chain on side stream; wsplit+GEMM1 on main ----
    cudaEventRecord(ev_fork, 0);
    cudaStreamWaitEvent(s_side, ev_fork, 0);

    zero_int2_kernel<<<(n + 255) / 256, 256, 0, s_side>>>(ideg_s, ideg_d, n);
    degree_kernel<<<(e + 255) / 256, 256, 0, s_side>>>(src, dst, e);
    scan1_kernel<<<nb, 1024, 0, s_side>>>(ideg_d, roff, bsums, n);
    scan2_kernel<<<1, 128, 0, s_side>>>(bsums, nb);
    scan3_kernel<<<(n + 255) / 256, 256, 0, s_side>>>(roff, cursor, bsums, n, e);
    csr_fill_kernel<<<(e + 255) / 256, 256, 0, s_side>>>(src, dst, cursor, csr, e);

    wsplit_kernel<<<64, 256>>>(W0, 128);                       // 128 kpairs (K=256)
    gemm_bf16_kernel<<<gblocks, 256>>>(x, tmp, n, 256);

    // ---- join ----
    cudaEventRecord(ev_join, s_side);
    cudaStreamWaitEvent(0, ev_join, 0);

    spmm_csr_kernel<<<sblocks, 256>>>(tmp, csr, roff, csrc, cdst, b0, hbuf, n, 1);

    wsplit_kernel<<<32, 256>>>(W1, 64);                        // 64 kpairs (K=128)
    gemm_bf16_kernel<<<gblocks, 256>>>(hbuf, tmp, n, 128);
    spmm_csr_kernel<<<sblocks, 256>>>(tmp, csr, roff, csrc, cdst, b1, out_h, n, 0);

    final_kernel<<<(n + 31) / 32, 256>>>(out_h, Wc, bc, out_logits, n);
}

// round 6
// speedup vs baseline: 3.8905x; 1.0656x over previous
#include <cuda_runtime.h>
#include <cuda_bf16.h>
#include <cuda_fp16.h>
#include <cstdint>

#define MAXN 100000
#define MAXE 1600000
#define HID 128
#define CLS 40

// ---------------- scratch (static device memory, no allocations) ----------------
__device__ int      g_ideg_src[MAXN];
__device__ int      g_ideg_dst[MAXN];
__device__ float    g_csrc[MAXN];
__device__ float    g_cdst[MAXN];
__device__ int      g_roff[MAXN + 1];
__device__ int      g_cursor[MAXN];
__device__ int      g_bsums[128];
__device__ int      g_csr[MAXE];
__device__ __half   g_tmp [(size_t)MAXN * HID];     // GEMM output, fp16
__device__ float    g_hbuf[(size_t)MAXN * HID];
__device__ uint32_t g_whi0[16384], g_wlo0[16384];   // W0 pre-split (128 kp x 128)
__device__ uint32_t g_whi1[8192],  g_wlo1[8192];    // W1 pre-split (64 kp x 128)

// ---------------- utilities ----------------
__global__ void zero_int2_kernel(int* __restrict__ a, int* __restrict__ b, int n) {
    int i = blockIdx.x * blockDim.x + threadIdx.x;
    if (i < n) { a[i] = 0; b[i] = 0; }
}

__global__ void degree_kernel(const int* __restrict__ src, const int* __restrict__ dst, int e) {
    int i = blockIdx.x * blockDim.x + threadIdx.x;
    if (i < e) {
        atomicAdd(&g_ideg_src[src[i]], 1);
        atomicAdd(&g_ideg_dst[dst[i]], 1);
    }
}

// ---------------- 3-phase exclusive scan of in-degrees -> CSR row offsets ----------------
__global__ void scan1_kernel(const int* __restrict__ deg, int* __restrict__ out,
                             int* __restrict__ bsums, int n) {
    __shared__ int sm[1024];
    int i = blockIdx.x * 1024 + threadIdx.x;
    int v = (i < n) ? deg[i] : 0;
    sm[threadIdx.x] = v;
    __syncthreads();
    for (int off = 1; off < 1024; off <<= 1) {
        int t = (threadIdx.x >= off) ? sm[threadIdx.x - off] : 0;
        __syncthreads();
        sm[threadIdx.x] += t;
        __syncthreads();
    }
    if (i < n) out[i] = sm[threadIdx.x] - v;
    if (threadIdx.x == 1023) bsums[blockIdx.x] = sm[1023];
}

__global__ void scan2_kernel(int* __restrict__ bsums, int nb) {
    __shared__ int sm[128];
    int t = threadIdx.x;
    int v = (t < nb) ? bsums[t] : 0;
    sm[t] = v;
    __syncthreads();
    for (int off = 1; off < 128; off <<= 1) {
        int u = (t >= off) ? sm[t - off] : 0;
        __syncthreads();
        sm[t] += u;
        __syncthreads();
    }
    if (t < nb) bsums[t] = sm[t] - v;
}

__global__ void scan3_kernel(int* __restrict__ roff, int* __restrict__ cursor,
                             const int* __restrict__ bsums, int n, int e) {
    int i = blockIdx.x * blockDim.x + threadIdx.x;
    if (i < n) {
        int v = roff[i] + bsums[i >> 10];
        roff[i] = v;
        cursor[i] = v;
        g_csrc[i] = rsqrtf(fmaxf((float)g_ideg_src[i], 1.f));
        g_cdst[i] = rsqrtf(fmaxf((float)g_ideg_dst[i], 1.f));
    }
    if (i == 0) roff[n] = e;
}

__global__ void csr_fill_kernel(const int* __restrict__ src, const int* __restrict__ dst,
                                int* __restrict__ cursor, int* __restrict__ csr, int e) {
    int i = blockIdx.x * blockDim.x + threadIdx.x;
    if (i < e) {
        int d = dst[i];
        int pos = atomicAdd(&cursor[d], 1);
        csr[pos] = src[i];
    }
}

// ---------------- bf16 split helpers ----------------
__device__ __forceinline__ void split2_pack(float x, float y, uint32_t& hi, uint32_t& lo) {
    __nv_bfloat16 hx = __float2bfloat16(x);
    __nv_bfloat16 hy = __float2bfloat16(y);
    float rx = x - __bfloat162float(hx);
    float ry = y - __bfloat162float(hy);
    __nv_bfloat162 h2 = __halves2bfloat162(hx, hy);
    __nv_bfloat162 l2 = __floats2bfloat162_rn(rx, ry);
    hi = *reinterpret_cast<uint32_t*>(&h2);
    lo = *reinterpret_cast<uint32_t*>(&l2);
}

__global__ void wsplit_kernel(const float* __restrict__ W, uint32_t* __restrict__ whi,
                              uint32_t* __restrict__ wlo, int kpairs) {
    int idx = blockIdx.x * blockDim.x + threadIdx.x;
    if (idx < kpairs * 128) {
        int kp = idx >> 7, n = idx & 127;
        float x = W[(size_t)(2 * kp) * 128 + n];
        float y = W[(size_t)(2 * kp + 1) * 128 + n];
        uint32_t h, l;
        split2_pack(x, y, h, l);
        whi[idx] = h;
        wlo[idx] = l;
    }
}

#define MMA_BF16(d, a, b0v, b1v)                                                  \
    asm volatile("mma.sync.aligned.m16n8k16.row.col.f32.bf16.bf16.f32 "           \
                 "{%0,%1,%2,%3}, {%4,%5,%6,%7}, {%8,%9}, {%0,%1,%2,%3};"          \
                 : "+f"((d)[0]), "+f"((d)[1]), "+f"((d)[2]), "+f"((d)[3])         \
                 : "r"((a)[0]), "r"((a)[1]), "r"((a)[2]), "r"((a)[3]),            \
                   "r"(b0v), "r"(b1v));

#define AS_STRIDE 20     // u32 per A row (16 kpairs + pad)
#define BS_STRIDE 136    // u32 per B kp row (128 + pad)
#define AS_BUF    2560   // 128 * AS_STRIDE
#define BS_BUF    2176   // 16 * BS_STRIDE
#define GEMM_SMEM ((2*AS_BUF*2 + 2*BS_BUF*2) * 4)   // 75776 bytes

#define CP_ASYNC16(dst_u32, src_ptr)                                              \
    asm volatile("cp.async.cg.shared.global [%0], [%1], 16;"                      \
                 :: "r"(dst_u32), "l"(src_ptr))
#define CP_COMMIT() asm volatile("cp.async.commit_group;" ::: "memory")
#define CP_WAIT0()  asm volatile("cp.async.wait_group 0;"  ::: "memory")

// ---------------- double-buffered bf16x3 tensor-core GEMM: C(fp16) = A[M,K](fp32) @ Wsplit
__global__ __launch_bounds__(256, 2)
void gemm_bf16_kernel(const float* __restrict__ A, const uint32_t* __restrict__ whi,
                      const uint32_t* __restrict__ wlo, __half* __restrict__ C,
                      int M, int K) {
    extern __shared__ uint32_t smem[];
    uint32_t* AsHi = smem;                         // [2][AS_BUF]
    uint32_t* AsLo = smem + 2 * AS_BUF;            // [2][AS_BUF]
    uint32_t* BsHi = smem + 4 * AS_BUF;            // [2][BS_BUF]
    uint32_t* BsLo = smem + 4 * AS_BUF + 2 * BS_BUF;

    const int tid  = threadIdx.x;
    const int warp = tid >> 5, lane = tid & 31;
    const int wm   = warp >> 1, wn = warp & 1;
    const int gid  = lane >> 2, tig = lane & 3;
    const int m0   = blockIdx.x * 128;
    const int nIter = K >> 5;

    float acc[2][8][4];
#pragma unroll
    for (int mt = 0; mt < 2; mt++)
#pragma unroll
        for (int nt = 0; nt < 8; nt++)
#pragma unroll
            for (int j = 0; j < 4; j++) acc[mt][nt][j] = 0.f;

    float4 aReg[4];

    // --- helpers (macros to keep everything inlined) ---
#define LD_A(k0)                                                                   \
    {                                                                              \
        _Pragma("unroll")                                                          \
        for (int l = 0; l < 4; l++) {                                              \
            int idx = tid + l * 256;                                               \
            int r = idx >> 3, c4 = idx & 7;                                        \
            aReg[l] = (m0 + r < M)                                                 \
                ? __ldg(reinterpret_cast<const float4*>(A + (size_t)(m0 + r) * K + (k0) + (c4 << 2))) \
                : make_float4(0.f, 0.f, 0.f, 0.f);                                 \
        }                                                                          \
    }

#define ST_A(dstHi, dstLo)                                                         \
    {                                                                              \
        _Pragma("unroll")                                                          \
        for (int l = 0; l < 4; l++) {                                              \
            int idx = tid + l * 256;                                               \
            int r = idx >> 3, c4 = idx & 7;                                        \
            uint32_t h0, l0, h1, l1;                                               \
            split2_pack(aReg[l].x, aReg[l].y, h0, l0);                             \
            split2_pack(aReg[l].z, aReg[l].w, h1, l1);                             \
            (dstHi)[r * AS_STRIDE + 2 * c4]     = h0;                              \
            (dstHi)[r * AS_STRIDE + 2 * c4 + 1] = h1;                              \
            (dstLo)[r * AS_STRIDE + 2 * c4]     = l0;                              \
            (dstLo)[r * AS_STRIDE + 2 * c4 + 1] = l1;                              \
        }                                                                          \
    }

#define CP_B(k0p, dstHi, dstLo)                                                    \
    {                                                                              \
        _Pragma("unroll")                                                          \
        for (int l = 0; l < 2; l++) {                                              \
            int idx = tid + l * 256;           /* 0..511: (kp, 16B-chunk) */       \
            int kp = idx >> 5, n16 = idx & 31;                                     \
            uint32_t dh = (uint32_t)__cvta_generic_to_shared((dstHi) + kp * BS_STRIDE + n16 * 4); \
            CP_ASYNC16(dh, whi + ((k0p) + kp) * 128 + n16 * 4);                    \
            uint32_t dl = (uint32_t)__cvta_generic_to_shared((dstLo) + kp * BS_STRIDE + n16 * 4); \
            CP_ASYNC16(dl, wlo + ((k0p) + kp) * 128 + n16 * 4);                    \
        }                                                                          \
    }

    // --- prologue: tile 0 into buffer 0 ---
    CP_B(0, BsHi, BsLo);
    CP_COMMIT();
    LD_A(0);
    ST_A(AsHi, AsLo);
    CP_WAIT0();
    __syncthreads();

    for (int it = 0; it < nIter; it++) {
        const int cur = it & 1, nxt = cur ^ 1;
        const bool more = (it + 1 < nIter);
        if (more) {
            LD_A((it + 1) << 5);
            CP_B((it + 1) << 4, BsHi + nxt * BS_BUF, BsLo + nxt * BS_BUF);
            CP_COMMIT();
        }

        const uint32_t* aHi = AsHi + cur * AS_BUF;
        const uint32_t* aLo = AsLo + cur * AS_BUF;
        const uint32_t* bHi = BsHi + cur * BS_BUF;
        const uint32_t* bLo = BsLo + cur * BS_BUF;

#pragma unroll
        for (int kkp = 0; kkp < 16; kkp += 8) {
            uint32_t ah[2][4], al[2][4];
#pragma unroll
            for (int mt = 0; mt < 2; mt++) {
                int rb = wm * 32 + mt * 16 + gid;
                int p0 = kkp + tig;
                ah[mt][0] = aHi[rb * AS_STRIDE + p0];
                ah[mt][1] = aHi[(rb + 8) * AS_STRIDE + p0];
                ah[mt][2] = aHi[rb * AS_STRIDE + p0 + 4];
                ah[mt][3] = aHi[(rb + 8) * AS_STRIDE + p0 + 4];
                al[mt][0] = aLo[rb * AS_STRIDE + p0];
                al[mt][1] = aLo[(rb + 8) * AS_STRIDE + p0];
                al[mt][2] = aLo[rb * AS_STRIDE + p0 + 4];
                al[mt][3] = aLo[(rb + 8) * AS_STRIDE + p0 + 4];
            }
#pragma unroll
            for (int nt = 0; nt < 8; nt++) {
                int cb = wn * 64 + nt * 8 + gid;
                uint32_t bh0 = bHi[(kkp + tig)     * BS_STRIDE + cb];
                uint32_t bh1 = bHi[(kkp + tig + 4) * BS_STRIDE + cb];
                uint32_t bl0 = bLo[(kkp + tig)     * BS_STRIDE + cb];
                uint32_t bl1 = bLo[(kkp + tig + 4) * BS_STRIDE + cb];
#pragma unroll
                for (int mt = 0; mt < 2; mt++) {
                    MMA_BF16(acc[mt][nt], ah[mt], bh0, bh1);
                    MMA_BF16(acc[mt][nt], al[mt], bh0, bh1);
                    MMA_BF16(acc[mt][nt], ah[mt], bl0, bl1);
                }
            }
        }

        if (more) {
            ST_A(AsHi + nxt * AS_BUF, AsLo + nxt * AS_BUF);
            CP_WAIT0();
        }
        __syncthreads();
    }

    // epilogue: store fp16 pairs (c_src applied later in SpMM gather)
#pragma unroll
    for (int mt = 0; mt < 2; mt++) {
        int r0 = m0 + wm * 32 + mt * 16 + gid;
        int r1 = r0 + 8;
#pragma unroll
        for (int nt = 0; nt < 8; nt++) {
            int c = wn * 64 + nt * 8 + 2 * tig;
            if (r0 < M) {
                __half2 o = __floats2half2_rn(acc[mt][nt][0], acc[mt][nt][1]);
                *reinterpret_cast<__half2*>(C + (size_t)r0 * 128 + c) = o;
            }
            if (r1 < M) {
                __half2 o = __floats2half2_rn(acc[mt][nt][2], acc[mt][nt][3]);
                *reinterpret_cast<__half2*>(C + (size_t)r1 * 128 + c) = o;
            }
        }
    }
#undef LD_A
#undef ST_A
#undef CP_B
}

// ---------------- CSR SpMM (fp16 gather, fp32 accum) ----------------
__global__ void spmm_csr_kernel(const __half* __restrict__ T, const int* __restrict__ csr,
                                const int* __restrict__ roff, const float* __restrict__ csrc,
                                const float* __restrict__ cdst,
                                const float* __restrict__ bias, float* __restrict__ out,
                                int n, int do_relu) {
    int w    = (blockIdx.x * blockDim.x + threadIdx.x) >> 5;
    int lane = threadIdx.x & 31;
    if (w >= n) return;
    int beg = __ldg(roff + w), end = __ldg(roff + w + 1);

    float4 acc = make_float4(0.f, 0.f, 0.f, 0.f);
    int i = beg;
    for (; i + 4 <= end; i += 4) {
        int s0 = __ldg(csr + i);
        int s1 = __ldg(csr + i + 1);
        int s2 = __ldg(csr + i + 2);
        int s3 = __ldg(csr + i + 3);
        float c0 = __ldg(csrc + s0);
        float c1 = __ldg(csrc + s1);
        float c2 = __ldg(csrc + s2);
        float c3 = __ldg(csrc + s3);
        uint2 u0 = *(reinterpret_cast<const uint2*>(T + (size_t)s0 * 128) + lane);
        uint2 u1 = *(reinterpret_cast<const uint2*>(T + (size_t)s1 * 128) + lane);
        uint2 u2 = *(reinterpret_cast<const uint2*>(T + (size_t)s2 * 128) + lane);
        uint2 u3 = *(reinterpret_cast<const uint2*>(T + (size_t)s3 * 128) + lane);
        float2 a0 = __half22float2(*reinterpret_cast<__half2*>(&u0.x));
        float2 b0v = __half22float2(*reinterpret_cast<__half2*>(&u0.y));
        float2 a1 = __half22float2(*reinterpret_cast<__half2*>(&u1.x));
        float2 b1v = __half22float2(*reinterpret_cast<__half2*>(&u1.y));
        float2 a2 = __half22float2(*reinterpret_cast<__half2*>(&u2.x));
        float2 b2v = __half22float2(*reinterpret_cast<__half2*>(&u2.y));
        float2 a3 = __half22float2(*reinterpret_cast<__half2*>(&u3.x));
        float2 b3v = __half22float2(*reinterpret_cast<__half2*>(&u3.y));
        acc.x += (a0.x * c0 + a1.x * c1) + (a2.x * c2 + a3.x * c3);
        acc.y += (a0.y * c0 + a1.y * c1) + (a2.y * c2 + a3.y * c3);
        acc.z += (b0v.x * c0 + b1v.x * c1) + (b2v.x * c2 + b3v.x * c3);
        acc.w += (b0v.y * c0 + b1v.y * c1) + (b2v.y * c2 + b3v.y * c3);
    }
    for (; i < end; i++) {
        int s = __ldg(csr + i);
        float c = __ldg(csrc + s);
        uint2 u = *(reinterpret_cast<const uint2*>(T + (size_t)s * 128) + lane);
        float2 a = __half22float2(*reinterpret_cast<__half2*>(&u.x));
        float2 b = __half22float2(*reinterpret_cast<__half2*>(&u.y));
        acc.x += a.x * c; acc.y += a.y * c; acc.z += b.x * c; acc.w += b.y * c;
    }
    float c = __ldg(cdst + w);
    float4 b = *reinterpret_cast<const float4*>(bias + (lane << 2));
    acc.x = acc.x * c + b.x;
    acc.y = acc.y * c + b.y;
    acc.z = acc.z * c + b.z;
    acc.w = acc.w * c + b.w;
    if (do_relu) {
        acc.x = fmaxf(acc.x, 0.f); acc.y = fmaxf(acc.y, 0.f);
        acc.z = fmaxf(acc.z, 0.f); acc.w = fmaxf(acc.w, 0.f);
    }
    *reinterpret_cast<float4*>(out + (size_t)w * 128 + (lane << 2)) = acc;
}

// ---------------- final: logits = relu(h) @ Wc + bc ----------------
__global__ void final_kernel(const float* __restrict__ h, const float* __restrict__ Wc,
                             const float* __restrict__ bc, float* __restrict__ out_logits, int n) {
    __shared__ float hs[32][HID + 1];
    __shared__ float Wcs[HID][CLS];
    __shared__ float bcs[CLS];

    const int tid = threadIdx.x;
    const int n0  = blockIdx.x * 32;

    for (int i = tid; i < HID * CLS; i += 256) Wcs[i / CLS][i % CLS] = Wc[i];
    if (tid < CLS) bcs[tid] = bc[tid];

    for (int i = tid; i < 32 * HID; i += 256) {
        int r = i >> 7, c = i & 127;
        int g = n0 + r;
        hs[r][c] = (g < n) ? fmaxf(h[(size_t)g * HID + c], 0.f) : 0.f;
    }
    __syncthreads();

    int r  = tid & 31;
    int cg = tid >> 5;
    int g  = n0 + r;
    if (g < n) {
        float acc[5];
#pragma unroll
        for (int j = 0; j < 5; j++) acc[j] = bcs[cg * 5 + j];
        for (int k = 0; k < HID; k++) {
            float a = hs[r][k];
#pragma unroll
            for (int j = 0; j < 5; j++) acc[j] = fmaf(a, Wcs[k][cg * 5 + j], acc[j]);
        }
#pragma unroll
        for (int j = 0; j < 5; j++) out_logits[(size_t)g * CLS + cg * 5 + j] = acc[j];
    }
}

// ---------------- launch ----------------
extern "C" void kernel_launch(void* const* d_in, const int* in_sizes, int n_in,
                              void* d_out, int out_size) {
    const float* x   = (const float*)d_in[0];
    const int*   src = (const int*)d_in[1];
    const int*   dst = (const int*)d_in[2];
    const float* W0  = (const float*)d_in[3];
    const float* b0  = (const float*)d_in[4];
    const float* W1  = (const float*)d_in[5];
    const float* b1  = (const float*)d_in[6];
    const float* Wc  = (const float*)d_in[7];
    const float* bc  = (const float*)d_in[8];

    const int n = in_sizes[0] / 256;
    const int e = in_sizes[1];

    int *ideg_s, *ideg_d, *roff, *cursor, *bsums, *csr;
    float *csrc, *cdst, *hbuf;
    __half* tmp;
    uint32_t *whi0, *wlo0, *whi1, *wlo1;
    cudaGetSymbolAddress((void**)&ideg_s, g_ideg_src);
    cudaGetSymbolAddress((void**)&ideg_d, g_ideg_dst);
    cudaGetSymbolAddress((void**)&roff,   g_roff);
    cudaGetSymbolAddress((void**)&cursor, g_cursor);
    cudaGetSymbolAddress((void**)&bsums,  g_bsums);
    cudaGetSymbolAddress((void**)&csr,    g_csr);
    cudaGetSymbolAddress((void**)&csrc,   g_csrc);
    cudaGetSymbolAddress((void**)&cdst,   g_cdst);
    cudaGetSymbolAddress((void**)&tmp,    g_tmp);
    cudaGetSymbolAddress((void**)&hbuf,   g_hbuf);
    cudaGetSymbolAddress((void**)&whi0,   g_whi0);
    cudaGetSymbolAddress((void**)&wlo0,   g_wlo0);
    cudaGetSymbolAddress((void**)&whi1,   g_whi1);
    cudaGetSymbolAddress((void**)&wlo1,   g_wlo1);

    float* out_h      = (float*)d_out;
    float* out_logits = out_h + (size_t)n * HID;

    static cudaStream_t s_side = nullptr;
    static cudaEvent_t  ev_fork = nullptr, ev_join = nullptr;
    if (s_side == nullptr) {
        cudaStreamCreateWithFlags(&s_side, cudaStreamNonBlocking);
        cudaEventCreateWithFlags(&ev_fork, cudaEventDisableTiming);
        cudaEventCreateWithFlags(&ev_join, cudaEventDisableTiming);
        cudaFuncSetAttribute(gemm_bf16_kernel,
                             cudaFuncAttributeMaxDynamicSharedMemorySize, GEMM_SMEM);
    }

    const int nb = (n + 1023) / 1024;
    const int gblocks = (n + 127) / 128;
    const int sblocks = (int)(((size_t)n * 32 + 255) / 256);

    // ---- fork: CSR/degree chain on side stream; weight splits + GEMM1 on main ----
    cudaEventRecord(ev_fork, 0);
    cudaStreamWaitEvent(s_side, ev_fork, 0);

    zero_int2_kernel<<<(n + 255) / 256, 256, 0, s_side>>>(ideg_s, ideg_d, n);
    degree_kernel<<<(e + 255) / 256, 256, 0, s_side>>>(src, dst, e);
    scan1_kernel<<<nb, 1024, 0, s_side>>>(ideg_d, roff, bsums, n);
    scan2_kernel<<<1, 128, 0, s_side>>>(bsums, nb);
    scan3_kernel<<<(n + 255) / 256, 256, 0, s_side>>>(roff, cursor, bsums, n, e);
    csr_fill_kernel<<<(e + 255) / 256, 256, 0, s_side>>>(src, dst, cursor, csr, e);

    wsplit_kernel<<<64, 256>>>(W0, whi0, wlo0, 128);
    wsplit_kernel<<<32, 256>>>(W1, whi1, wlo1, 64);
    gemm_bf16_kernel<<<gblocks, 256, GEMM_SMEM>>>(x, whi0, wlo0, tmp, n, 256);

    // ---- join ----
    cudaEventRecord(ev_join, s_side);
    cudaStreamWaitEvent(0, ev_join, 0);

    spmm_csr_kernel<<<sblocks, 256>>>(tmp, csr, roff, csrc, cdst, b0, hbuf, n, 1);

    gemm_bf16_kernel<<<gblocks, 256, GEMM_SMEM>>>(hbuf, whi1, wlo1, tmp, n, 128);
    spmm_csr_kernel<<<sblocks, 256>>>(tmp, csr, roff, csrc, cdst, b1, out_h, n, 0);

    final_kernel<<<(n + 31) / 32, 256>>>(out_h, Wc, bc, out_logits, n);
}